// round 10
// baseline (speedup 1.0000x reference)
#include <cuda_runtime.h>
#include <cstdint>

#define BATCH 8
#define NPTS  8192
#define NCENT 512
#define KSPLIT_PV 8

// ---------------- scratch (device globals: no allocations allowed) ----------
__device__ float g_support[BATCH * 64 * NPTS];
__device__ float g_h1[BATCH * 128 * NPTS];
__device__ float g_h2[BATCH * 256 * NPTS];
__device__ float g_feat[BATCH * 256 * NPTS];
__device__ float g_kbuf[BATCH * 256 * NPTS];
__device__ float g_vbuf[BATCH * 256 * NPTS];
__device__ float g_qbuf[BATCH * 256 * NCENT];
__device__ float g_cent[BATCH * 256 * NCENT];
__device__ float g_logits[BATCH * NCENT * NPTS];
__device__ float g_attpart[BATCH * KSPLIT_PV * 256 * NCENT];
__device__ float g_att[BATCH * 256 * NCENT];
__device__ int   g_idx[BATCH * NCENT];
__device__ float g_bns1[128], g_bnh1[128];
__device__ float g_bns2[256], g_bnh2[256];
// FPS cross-CTA coordination (reset by fps_init each call)
__device__ unsigned long long g_best[BATCH * 8];   // 8-slot ring per batch
__device__ unsigned int       g_count[BATCH * 2];  // monotonic, per parity

__device__ __forceinline__ void cp_async16(uint32_t dst, const void* src) {
    asm volatile("cp.async.cg.shared.global [%0], [%1], 16;\n" :: "r"(dst), "l"(src));
}
__device__ __forceinline__ void cp_commit() {
    asm volatile("cp.async.commit_group;\n");
}
__device__ __forceinline__ void cp_wait_all() {
    asm volatile("cp.async.wait_group 0;\n" ::: "memory");
}

// ---------------- init: zero FPS coordination state --------------------------
__global__ void fps_init_kernel()
{
    int t = threadIdx.x;
    if (t < BATCH * 8) g_best[t] = 0ull;
    if (t < BATCH * 2) g_count[t] = 0u;
}

// ---------------- build support = concat(xyz, point_features) ---------------
__global__ void __launch_bounds__(256) support_kernel(
    const float* __restrict__ xyz, const float* __restrict__ pf)
{
    int total = BATCH * 64 * (NPTS / 4);
    for (int v = blockIdx.x * blockDim.x + threadIdx.x; v < total; v += gridDim.x * blockDim.x) {
        int b = v >> 17;
        int rem = v & 131071;
        int c = rem >> 11;
        int nv = rem & 2047;
        float4 f;
        if (c < 3)
            f = reinterpret_cast<const float4*>(xyz + ((long long)b * 3 + c) * NPTS)[nv];
        else
            f = reinterpret_cast<const float4*>(pf + ((long long)b * 61 + (c - 3)) * NPTS)[nv];
        reinterpret_cast<float4*>(g_support)[v] = f;
    }
}

// ---------------- FPS (unchanged from passing round 7) ----------------------
__global__ void __launch_bounds__(512, 1) fps_kernel(const int* __restrict__ far0)
{
    __shared__ float cent[64];
    __shared__ unsigned long long warp_best[16];
    __shared__ int s_far;

    int rank = blockIdx.x & 15;
    int b = blockIdx.x >> 4;
    int t = threadIdx.x;
    const float* sb = g_support + (long long)b * 64 * NPTS;
    int myn = (rank << 9) + t;

    float p[64];
#pragma unroll
    for (int c = 0; c < 64; ++c) p[c] = sb[(c << 13) + myn];

    float distance = 1e10f;
    int far = far0[b];
    if (rank == 0 && t == 0) g_idx[b * NCENT] = far;

    unsigned long long* best = g_best + b * 8;
    volatile unsigned int* cnt = (volatile unsigned int*)(g_count + b * 2);

    for (int m = 0; m < NCENT - 1; ++m) {
        if (t < 64) cent[t] = sb[(t << 13) + far];
        __syncthreads();
        double dd = 0.0;
#pragma unroll
        for (int c = 0; c < 64; ++c) {
            double df = (double)p[c] - (double)cent[c];
            dd = fma(df, df, dd);
        }
        float d = (float)dd;                  // correctly-rounded fp32 distance
        distance = fminf(distance, d);
        unsigned long long key =
            ((unsigned long long)__float_as_uint(distance) << 32)
            | (unsigned long long)(0xFFFFFFFFu - (unsigned)myn);
#pragma unroll
        for (int o = 16; o > 0; o >>= 1) {
            unsigned long long ok = __shfl_xor_sync(0xFFFFFFFFu, key, o);
            key = (ok > key) ? ok : key;
        }
        if ((t & 31) == 0) warp_best[t >> 5] = key;
        __syncthreads();
        if (t == 0) {
            unsigned long long kk = warp_best[0];
#pragma unroll
            for (int w = 1; w < 16; ++w) {
                unsigned long long o2 = warp_best[w];
                kk = (o2 > kk) ? o2 : kk;
            }
            int slot = m & 7;
            int par = m & 1;
            atomicMax(best + slot, kk);
            __threadfence();
            atomicAdd((unsigned int*)(g_count + b * 2 + par), 1u);
            unsigned target = 16u * (unsigned)(m / 2 + 1);
            while (cnt[par] < target) { }
            __threadfence();
            unsigned long long win = best[slot];
            int f = (int)(0xFFFFFFFFu - (unsigned)(win & 0xFFFFFFFFull));
            s_far = f;
            if (rank == 0) {
                g_idx[b * NCENT + m + 1] = f;
                best[(m + 4) & 7] = 0ull;
            }
        }
        __syncthreads();
        far = s_far;
    }
}

// ---------------- pipelined SGEMM, 128x128 tile, 8x8/thread, 2-stage --------
// cp.async global->smem double buffering + register double-buffered fragments
// (LDS for kk+1 overlaps FFMA for kk). FFMA order per accumulator identical
// to prior passing kernels -> bitwise-identical results.
// AMODE 0: A[M,K] row-major (register-staged transpose into As[k][m]).
// AMODE 1: A[K,M]            (cp.async direct into As[k][m]).
// BMODE 0: B[K,N]            (cp.async direct into Bs[k][n]).
// BMODE 1: B[N,K]            (register-staged transpose into Bs[k][n]).
// C = scale*(A*B) + bias[row] + addbuf. ksplit: raw partials per z-slab.
template<int AMODE, int BMODE>
__global__ void __launch_bounds__(256, 2) sgemm_kernel(
    const float* __restrict__ A, const float* __restrict__ Bm, float* __restrict__ C,
    int Md, int Nd, int Kd,
    long long sA, long long sB, long long sC,
    const float* __restrict__ bias, const float* __restrict__ addbuf,
    float scale, int ksplit)
{
    __shared__ float As[2][16][128];
    __shared__ float Bs[2][16][128];
    int bz = blockIdx.z;
    int batch = bz / ksplit;
    int ks = bz - batch * ksplit;
    int kchunk = Kd / ksplit;
    int k0 = ks * kchunk;
    int ntiles = kchunk >> 4;
    const float* Ab = A + (long long)batch * sA;
    const float* Bb = Bm + (long long)batch * sB;
    float* Cb = C + (long long)bz * sC;
    int bm0 = blockIdx.y * 128;
    int bn0 = blockIdx.x * 128;
    int t = threadIdx.x;
    int row0 = (t >> 4) << 3;
    int col0 = (t & 15) << 3;

    uint32_t sAs = (uint32_t)__cvta_generic_to_shared(&As[0][0][0]);
    uint32_t sBs = (uint32_t)__cvta_generic_to_shared(&Bs[0][0][0]);

    float4 fa0, fa1, fb0, fb1;

    auto issueA = [&](int bb, int kt) {
        if (AMODE == 0) {
            int v0 = t, v1 = t + 256;
            fa0 = *reinterpret_cast<const float4*>(
                Ab + (long long)(bm0 + (v0 >> 2)) * Kd + kt + ((v0 & 3) << 2));
            fa1 = *reinterpret_cast<const float4*>(
                Ab + (long long)(bm0 + (v1 >> 2)) * Kd + kt + ((v1 & 3) << 2));
        } else {
#pragma unroll
            for (int i2 = 0; i2 < 2; ++i2) {
                int v = t + i2 * 256;
                int kk = v >> 5, mv = (v & 31) << 2;
                cp_async16(sAs + (uint32_t)((((bb << 11) | (kk << 7) | mv)) << 2),
                           Ab + (long long)(kt + kk) * Md + bm0 + mv);
            }
        }
    };
    auto storeA = [&](int bb) {
        if (AMODE == 0) {
            int v0 = t, r0 = v0 >> 2, k0v = (v0 & 3) << 2;
            As[bb][k0v + 0][r0] = fa0.x; As[bb][k0v + 1][r0] = fa0.y;
            As[bb][k0v + 2][r0] = fa0.z; As[bb][k0v + 3][r0] = fa0.w;
            int v1 = t + 256, r1 = v1 >> 2, k1v = (v1 & 3) << 2;
            As[bb][k1v + 0][r1] = fa1.x; As[bb][k1v + 1][r1] = fa1.y;
            As[bb][k1v + 2][r1] = fa1.z; As[bb][k1v + 3][r1] = fa1.w;
        }
    };
    auto issueB = [&](int bb, int kt) {
        if (BMODE == 0) {
#pragma unroll
            for (int i2 = 0; i2 < 2; ++i2) {
                int v = t + i2 * 256;
                int kk = v >> 5, nv = (v & 31) << 2;
                cp_async16(sBs + (uint32_t)((((bb << 11) | (kk << 7) | nv)) << 2),
                           Bb + (long long)(kt + kk) * Nd + bn0 + nv);
            }
        } else {
            int v0 = t, v1 = t + 256;
            fb0 = *reinterpret_cast<const float4*>(
                Bb + (long long)(bn0 + (v0 >> 2)) * Kd + kt + ((v0 & 3) << 2));
            fb1 = *reinterpret_cast<const float4*>(
                Bb + (long long)(bn0 + (v1 >> 2)) * Kd + kt + ((v1 & 3) << 2));
        }
    };
    auto storeB = [&](int bb) {
        if (BMODE == 1) {
            int v0 = t, n0 = v0 >> 2, k0v = (v0 & 3) << 2;
            Bs[bb][k0v + 0][n0] = fb0.x; Bs[bb][k0v + 1][n0] = fb0.y;
            Bs[bb][k0v + 2][n0] = fb0.z; Bs[bb][k0v + 3][n0] = fb0.w;
            int v1 = t + 256, n1 = v1 >> 2, k1v = (v1 & 3) << 2;
            Bs[bb][k1v + 0][n1] = fb1.x; Bs[bb][k1v + 1][n1] = fb1.y;
            Bs[bb][k1v + 2][n1] = fb1.z; Bs[bb][k1v + 3][n1] = fb1.w;
        }
    };

    float acc[8][8];
#pragma unroll
    for (int i = 0; i < 8; ++i)
#pragma unroll
        for (int j = 0; j < 8; ++j) acc[i][j] = 0.f;

    // prologue: stage tile 0 into buffer 0
    issueA(0, k0); issueB(0, k0);
    storeA(0); storeB(0);
    cp_commit();
    cp_wait_all();
    __syncthreads();

    float ra[2][8], rb[2][8];
    int buf = 0;
    for (int it = 0; it < ntiles; ++it) {
        bool hn = (it + 1 < ntiles);
        if (hn) {
            int ktn = k0 + ((it + 1) << 4);
            issueA(buf ^ 1, ktn);
            issueB(buf ^ 1, ktn);
            cp_commit();
        }
        const float (*Asb)[128] = As[buf];
        const float (*Bsb)[128] = Bs[buf];
        // fragment prologue (kk = 0)
        *reinterpret_cast<float4*>(&ra[0][0]) = *reinterpret_cast<const float4*>(&Asb[0][row0]);
        *reinterpret_cast<float4*>(&ra[0][4]) = *reinterpret_cast<const float4*>(&Asb[0][row0 + 4]);
        *reinterpret_cast<float4*>(&rb[0][0]) = *reinterpret_cast<const float4*>(&Bsb[0][col0]);
        *reinterpret_cast<float4*>(&rb[0][4]) = *reinterpret_cast<const float4*>(&Bsb[0][col0 + 4]);
#pragma unroll
        for (int kk = 0; kk < 16; ++kk) {
            int cur = kk & 1;
            int nxt = cur ^ 1;
            if (kk < 15) {
                *reinterpret_cast<float4*>(&ra[nxt][0]) =
                    *reinterpret_cast<const float4*>(&Asb[kk + 1][row0]);
                *reinterpret_cast<float4*>(&ra[nxt][4]) =
                    *reinterpret_cast<const float4*>(&Asb[kk + 1][row0 + 4]);
                *reinterpret_cast<float4*>(&rb[nxt][0]) =
                    *reinterpret_cast<const float4*>(&Bsb[kk + 1][col0]);
                *reinterpret_cast<float4*>(&rb[nxt][4]) =
                    *reinterpret_cast<const float4*>(&Bsb[kk + 1][col0 + 4]);
            }
#pragma unroll
            for (int i = 0; i < 8; ++i)
#pragma unroll
                for (int j = 0; j < 8; ++j)
                    acc[i][j] = fmaf(ra[cur][i], rb[cur][j], acc[i][j]);
        }
        if (hn) {
            storeA(buf ^ 1);
            storeB(buf ^ 1);
            cp_wait_all();
            __syncthreads();
            buf ^= 1;
        }
    }

#pragma unroll
    for (int i = 0; i < 8; ++i) {
        int r = bm0 + row0 + i;
        float bv = bias ? bias[r] : 0.f;
#pragma unroll
        for (int jv = 0; jv < 2; ++jv) {
            int cidx = bn0 + col0 + (jv << 2);
            float4 o;
            o.x = acc[i][jv * 4 + 0] * scale + bv;
            o.y = acc[i][jv * 4 + 1] * scale + bv;
            o.z = acc[i][jv * 4 + 2] * scale + bv;
            o.w = acc[i][jv * 4 + 3] * scale + bv;
            if (addbuf) {
                const float4 a4 = *reinterpret_cast<const float4*>(
                    addbuf + (long long)batch * sC + (long long)r * Nd + cidx);
                o.x += a4.x; o.y += a4.y; o.z += a4.z; o.w += a4.w;
            }
            *reinterpret_cast<float4*>(Cb + (long long)r * Nd + cidx) = o;
        }
    }
}

// ---------------- BatchNorm (train-mode) per-channel affine -----------------
__global__ void __launch_bounds__(256) bn_stats_kernel(
    const float* __restrict__ x, const float* __restrict__ gamma,
    const float* __restrict__ beta, float* __restrict__ scale,
    float* __restrict__ shift, int Cd)
{
    __shared__ float rs[8], rq[8];
    int c = blockIdx.x;
    int t = threadIdx.x;
    float s = 0.f, q = 0.f;
    for (int b = 0; b < BATCH; ++b) {
        const float4* p = reinterpret_cast<const float4*>(x + ((long long)b * Cd + c) * NPTS);
        for (int v = t; v < NPTS / 4; v += 256) {
            float4 f = p[v];
            s += f.x + f.y + f.z + f.w;
            q += f.x * f.x + f.y * f.y + f.z * f.z + f.w * f.w;
        }
    }
#pragma unroll
    for (int o = 16; o; o >>= 1) {
        s += __shfl_xor_sync(0xFFFFFFFFu, s, o);
        q += __shfl_xor_sync(0xFFFFFFFFu, q, o);
    }
    if ((t & 31) == 0) { rs[t >> 5] = s; rq[t >> 5] = q; }
    __syncthreads();
    if (t == 0) {
        float S = 0.f, Q = 0.f;
#pragma unroll
        for (int w = 0; w < 8; ++w) { S += rs[w]; Q += rq[w]; }
        const float inv = 1.f / (float)(BATCH * NPTS);
        float mean = S * inv;
        float var = Q * inv - mean * mean;
        float rstd = rsqrtf(var + 1e-5f);
        float g = gamma[c];
        scale[c] = rstd * g;
        shift[c] = beta[c] - mean * rstd * g;
    }
}

// ---------------- BN affine + LeakyReLU, in-place ---------------------------
__global__ void __launch_bounds__(256) bn_apply_kernel(
    float* __restrict__ x, const float* __restrict__ scale,
    const float* __restrict__ shift, int Cd)
{
    int total = BATCH * Cd * (NPTS / 4);
    for (int v = blockIdx.x * blockDim.x + threadIdx.x; v < total; v += gridDim.x * blockDim.x) {
        int c = (v >> 11) % Cd;     // 2048 float4 per channel row
        float s = scale[c], sh = shift[c];
        float4 f = reinterpret_cast<float4*>(x)[v];
        f.x = f.x * s + sh; f.y = f.y * s + sh;
        f.z = f.z * s + sh; f.w = f.w * s + sh;
        f.x = f.x > 0.f ? f.x : 0.2f * f.x;
        f.y = f.y > 0.f ? f.y : 0.2f * f.y;
        f.z = f.z > 0.f ? f.z : 0.2f * f.z;
        f.w = f.w > 0.f ? f.w : 0.2f * f.w;
        reinterpret_cast<float4*>(x)[v] = f;
    }
}

// ---------------- gather centroids (feat) and new_xyz -----------------------
__global__ void __launch_bounds__(256) gather_kernel(
    const float* __restrict__ xyz, float* __restrict__ out_xyz)
{
    int v = blockIdx.x * blockDim.x + threadIdx.x;
    if (v < BATCH * 256 * NCENT) {
        int b = v >> 17;
        int rem = v & 131071;
        int c = rem >> 9;
        int m = rem & 511;
        int id = g_idx[b * NCENT + m];
        g_cent[v] = g_feat[((long long)b * 256 + c) * NPTS + id];
    }
    if (v < BATCH * 3 * NCENT) {
        int b = v / (3 * NCENT);
        int rem = v - b * 3 * NCENT;
        int c = rem >> 9;
        int m = rem & 511;
        int id = g_idx[b * NCENT + m];
        out_xyz[v] = xyz[((long long)b * 3 + c) * NPTS + id];
    }
}

// ---------------- softmax over last dim, rows in registers ------------------
__global__ void __launch_bounds__(256) softmax_kernel()
{
    __shared__ float red[8];
    long long row = blockIdx.x;
    float4* p = reinterpret_cast<float4*>(g_logits + row * NPTS);
    int t = threadIdx.x;
    float4 v[8];
#pragma unroll
    for (int i = 0; i < 8; ++i) v[i] = p[t + (i << 8)];
    float mx = -1e30f;
#pragma unroll
    for (int i = 0; i < 8; ++i)
        mx = fmaxf(mx, fmaxf(fmaxf(v[i].x, v[i].y), fmaxf(v[i].z, v[i].w)));
#pragma unroll
    for (int o = 16; o; o >>= 1) mx = fmaxf(mx, __shfl_xor_sync(0xFFFFFFFFu, mx, o));
    if ((t & 31) == 0) red[t >> 5] = mx;
    __syncthreads();
#pragma unroll
    for (int w = 0; w < 8; ++w) mx = fmaxf(mx, red[w]);
    __syncthreads();
    float s = 0.f;
#pragma unroll
    for (int i = 0; i < 8; ++i) {
        v[i].x = __expf(v[i].x - mx); v[i].y = __expf(v[i].y - mx);
        v[i].z = __expf(v[i].z - mx); v[i].w = __expf(v[i].w - mx);
        s += v[i].x + v[i].y + v[i].z + v[i].w;
    }
#pragma unroll
    for (int o = 16; o; o >>= 1) s += __shfl_xor_sync(0xFFFFFFFFu, s, o);
    if ((t & 31) == 0) red[t >> 5] = s;
    __syncthreads();
    s = 0.f;
#pragma unroll
    for (int w = 0; w < 8; ++w) s += red[w];
    float inv = 1.f / s;
#pragma unroll
    for (int i = 0; i < 8; ++i) {
        v[i].x *= inv; v[i].y *= inv; v[i].z *= inv; v[i].w *= inv;
        p[t + (i << 8)] = v[i];
    }
}

// ---------------- split-K reduction (KSPLIT_PV slabs) -----------------------
__global__ void __launch_bounds__(256) reduceK_kernel()
{
    int v = blockIdx.x * blockDim.x + threadIdx.x;   // float4 index
    int total = BATCH * 256 * NCENT / 4;             // 262144
    if (v >= total) return;
    int b = v >> 15;                                  // 32768 f4 per batch
    int i = v & 32767;
    const float4* pp = reinterpret_cast<const float4*>(g_attpart);
    float4 s = pp[((long long)b * KSPLIT_PV + 0) * 32768 + i];
#pragma unroll
    for (int ks = 1; ks < KSPLIT_PV; ++ks) {
        float4 x = pp[((long long)b * KSPLIT_PV + ks) * 32768 + i];
        s.x += x.x; s.y += x.y; s.z += x.z; s.w += x.w;
    }
    reinterpret_cast<float4*>(g_att)[v] = s;
}

// ---------------- host launcher ---------------------------------------------
static float* sym(const void* s) {
    void* p = nullptr;
    cudaGetSymbolAddress(&p, (const void*)s);
    return (float*)p;
}

extern "C" void kernel_launch(void* const* d_in, const int* in_sizes, int n_in,
                              void* d_out, int out_size)
{
    const float* xyz = (const float*)d_in[0];
    const float* pf  = (const float*)d_in[1];
    const float* w1  = (const float*)d_in[2];
    const float* b1  = (const float*)d_in[3];
    const float* g1  = (const float*)d_in[4];
    const float* be1 = (const float*)d_in[5];
    const float* w2  = (const float*)d_in[6];
    const float* b2  = (const float*)d_in[7];
    const float* g2  = (const float*)d_in[8];
    const float* be2 = (const float*)d_in[9];
    const float* w3  = (const float*)d_in[10];
    const float* b3  = (const float*)d_in[11];
    const float* wq  = (const float*)d_in[12];
    const float* wk  = (const float*)d_in[13];
    const float* wv  = (const float*)d_in[14];
    const float* wo  = (const float*)d_in[15];
    const int*   far0 = (const int*)d_in[16];
    float* out = (float*)d_out;

    float* p_sup  = sym(g_support);
    float* p_h1   = sym(g_h1);
    float* p_h2   = sym(g_h2);
    float* p_feat = sym(g_feat);
    float* p_k    = sym(g_kbuf);
    float* p_v    = sym(g_vbuf);
    float* p_q    = sym(g_qbuf);
    float* p_cent = sym(g_cent);
    float* p_log  = sym(g_logits);
    float* p_ap   = sym(g_attpart);
    float* p_att  = sym(g_att);
    float* p_s1   = sym(g_bns1);
    float* p_sh1  = sym(g_bnh1);
    float* p_s2   = sym(g_bns2);
    float* p_sh2  = sym(g_bnh2);

    // 0. reset FPS coordination state (device globals persist across replays)
    fps_init_kernel<<<1, 64>>>();

    // 1. support = concat(xyz, point_features)
    support_kernel<<<1024, 256>>>(xyz, pf);

    // 2. FPS: 128 persistent CTAs (16 per batch), gmem barriers
    fps_kernel<<<128, 512>>>(far0);

    // 3. h1 = w1 @ support + b1
    sgemm_kernel<0, 0><<<dim3(64, 1, 8), 256>>>(
        w1, p_sup, p_h1, 128, NPTS, 64,
        0LL, 64LL * NPTS, 128LL * NPTS,
        b1, nullptr, 1.f, 1);

    // 4. BN1 stats + apply (in-place lrelu(bn(h1)))
    bn_stats_kernel<<<128, 256>>>(p_h1, g1, be1, p_s1, p_sh1, 128);
    bn_apply_kernel<<<2048, 256>>>(p_h1, p_s1, p_sh1, 128);

    // 5. h2 = w2 @ h1' + b2
    sgemm_kernel<0, 0><<<dim3(64, 2, 8), 256>>>(
        w2, p_h1, p_h2, 256, NPTS, 128,
        0LL, 128LL * NPTS, 256LL * NPTS,
        b2, nullptr, 1.f, 1);

    // 6. BN2 stats + apply
    bn_stats_kernel<<<256, 256>>>(p_h2, g2, be2, p_s2, p_sh2, 256);
    bn_apply_kernel<<<4096, 256>>>(p_h2, p_s2, p_sh2, 256);

    // 7. feat = w3 @ h2' + b3
    sgemm_kernel<0, 0><<<dim3(64, 2, 8), 256>>>(
        w3, p_h2, p_feat, 256, NPTS, 256,
        0LL, 256LL * NPTS, 256LL * NPTS,
        b3, nullptr, 1.f, 1);

    // 8. gather centroids + new_xyz (new_xyz = first 12288 floats of out)
    gather_kernel<<<4096, 256>>>(xyz, out);

    // 9/10. k = wk @ feat ; v = wv @ feat
    sgemm_kernel<0, 0><<<dim3(64, 2, 8), 256>>>(
        wk, p_feat, p_k, 256, NPTS, 256,
        0LL, 256LL * NPTS, 256LL * NPTS,
        nullptr, nullptr, 1.f, 1);
    sgemm_kernel<0, 0><<<dim3(64, 2, 8), 256>>>(
        wv, p_feat, p_v, 256, NPTS, 256,
        0LL, 256LL * NPTS, 256LL * NPTS,
        nullptr, nullptr, 1.f, 1);

    // 11. q = wq @ centroids
    sgemm_kernel<0, 0><<<dim3(4, 2, 8), 256>>>(
        wq, p_cent, p_q, 256, NCENT, 256,
        0LL, 256LL * NCENT, 256LL * NCENT,
        nullptr, nullptr, 1.f, 1);

    // 12. logits = (q^T k) / 16
    sgemm_kernel<1, 0><<<dim3(64, 4, 8), 256>>>(
        p_q, p_k, p_log, NCENT, NPTS, 256,
        256LL * NCENT, 256LL * NPTS, (long long)NCENT * NPTS,
        nullptr, nullptr, 0.0625f, 1);

    // 13. softmax over N
    softmax_kernel<<<BATCH * NCENT, 256>>>();

    // 14. att1 = probs @ v^T  (split-K)
    sgemm_kernel<0, 1><<<dim3(4, 2, 8 * KSPLIT_PV), 256>>>(
        p_v, p_log, p_ap, 256, NCENT, NPTS,
        256LL * NPTS, (long long)NCENT * NPTS, 256LL * NCENT,
        nullptr, nullptr, 1.f, KSPLIT_PV);

    // 15. reduce split-K partials
    reduceK_kernel<<<1024, 256>>>();

    // 16. out2 = centroids + wo @ att1 (written into out + 12288)
    sgemm_kernel<0, 0><<<dim3(4, 2, 8), 256>>>(
        wo, p_att, out + BATCH * 3 * NCENT, 256, NCENT, 256,
        0LL, 256LL * NCENT, 256LL * NCENT,
        nullptr, p_cent, 1.f, 1);
}

// round 11
// speedup vs baseline: 1.0024x; 1.0024x over previous
#include <cuda_runtime.h>
#include <cstdint>

#define BATCH 8
#define NPTS  8192
#define NCENT 512
#define KSPLIT_PV 8

// ---------------- scratch (device globals: no allocations allowed) ----------
__device__ float g_support[BATCH * 64 * NPTS];
__device__ float g_h1[BATCH * 128 * NPTS];
__device__ float g_h2[BATCH * 256 * NPTS];
__device__ float g_feat[BATCH * 256 * NPTS];
__device__ float g_kbuf[BATCH * 256 * NPTS];
__device__ float g_vbuf[BATCH * 256 * NPTS];
__device__ float g_qbuf[BATCH * 256 * NCENT];
__device__ float g_cent[BATCH * 256 * NCENT];
__device__ float g_logits[BATCH * NCENT * NPTS];
__device__ float g_attpart[BATCH * KSPLIT_PV * 256 * NCENT];
__device__ float g_att[BATCH * 256 * NCENT];
__device__ int   g_idx[BATCH * NCENT];
__device__ float g_bns1[128], g_bnh1[128];
__device__ float g_bns2[256], g_bnh2[256];
// FPS cross-CTA coordination (reset by fps_init each call)
__device__ unsigned long long g_best[BATCH * 8];   // 8-slot ring per batch
__device__ unsigned int       g_count[BATCH * 2];  // monotonic, per parity

__device__ __forceinline__ void cp_async16(uint32_t dst, const void* src) {
    asm volatile("cp.async.cg.shared.global [%0], [%1], 16;\n" :: "r"(dst), "l"(src));
}
__device__ __forceinline__ void cp_commit() {
    asm volatile("cp.async.commit_group;\n");
}
__device__ __forceinline__ void cp_wait_all() {
    asm volatile("cp.async.wait_group 0;\n" ::: "memory");
}

// ---------------- init: zero FPS coordination state --------------------------
__global__ void fps_init_kernel()
{
    int t = threadIdx.x;
    if (t < BATCH * 8) g_best[t] = 0ull;
    if (t < BATCH * 2) g_count[t] = 0u;
}

// ---------------- build support = concat(xyz, point_features) ---------------
__global__ void __launch_bounds__(256) support_kernel(
    const float* __restrict__ xyz, const float* __restrict__ pf)
{
    int total = BATCH * 64 * (NPTS / 4);
    for (int v = blockIdx.x * blockDim.x + threadIdx.x; v < total; v += gridDim.x * blockDim.x) {
        int b = v >> 17;
        int rem = v & 131071;
        int c = rem >> 11;
        int nv = rem & 2047;
        float4 f;
        if (c < 3)
            f = reinterpret_cast<const float4*>(xyz + ((long long)b * 3 + c) * NPTS)[nv];
        else
            f = reinterpret_cast<const float4*>(pf + ((long long)b * 61 + (c - 3)) * NPTS)[nv];
        reinterpret_cast<float4*>(g_support)[v] = f;
    }
}

// ---------------- FPS (unchanged from passing round 7) ----------------------
__global__ void __launch_bounds__(512, 1) fps_kernel(const int* __restrict__ far0)
{
    __shared__ float cent[64];
    __shared__ unsigned long long warp_best[16];
    __shared__ int s_far;

    int rank = blockIdx.x & 15;
    int b = blockIdx.x >> 4;
    int t = threadIdx.x;
    const float* sb = g_support + (long long)b * 64 * NPTS;
    int myn = (rank << 9) + t;

    float p[64];
#pragma unroll
    for (int c = 0; c < 64; ++c) p[c] = sb[(c << 13) + myn];

    float distance = 1e10f;
    int far = far0[b];
    if (rank == 0 && t == 0) g_idx[b * NCENT] = far;

    unsigned long long* best = g_best + b * 8;
    volatile unsigned int* cnt = (volatile unsigned int*)(g_count + b * 2);

    for (int m = 0; m < NCENT - 1; ++m) {
        if (t < 64) cent[t] = sb[(t << 13) + far];
        __syncthreads();
        double dd = 0.0;
#pragma unroll
        for (int c = 0; c < 64; ++c) {
            double df = (double)p[c] - (double)cent[c];
            dd = fma(df, df, dd);
        }
        float d = (float)dd;                  // correctly-rounded fp32 distance
        distance = fminf(distance, d);
        unsigned long long key =
            ((unsigned long long)__float_as_uint(distance) << 32)
            | (unsigned long long)(0xFFFFFFFFu - (unsigned)myn);
#pragma unroll
        for (int o = 16; o > 0; o >>= 1) {
            unsigned long long ok = __shfl_xor_sync(0xFFFFFFFFu, key, o);
            key = (ok > key) ? ok : key;
        }
        if ((t & 31) == 0) warp_best[t >> 5] = key;
        __syncthreads();
        if (t == 0) {
            unsigned long long kk = warp_best[0];
#pragma unroll
            for (int w = 1; w < 16; ++w) {
                unsigned long long o2 = warp_best[w];
                kk = (o2 > kk) ? o2 : kk;
            }
            int slot = m & 7;
            int par = m & 1;
            atomicMax(best + slot, kk);
            __threadfence();
            atomicAdd((unsigned int*)(g_count + b * 2 + par), 1u);
            unsigned target = 16u * (unsigned)(m / 2 + 1);
            while (cnt[par] < target) { }
            __threadfence();
            unsigned long long win = best[slot];
            int f = (int)(0xFFFFFFFFu - (unsigned)(win & 0xFFFFFFFFull));
            s_far = f;
            if (rank == 0) {
                g_idx[b * NCENT + m + 1] = f;
                best[(m + 4) & 7] = 0ull;
            }
        }
        __syncthreads();
        far = s_far;
    }
}

// ---------------- pipelined SGEMM, 128x128 tile, 8x8/thread, 2-stage --------
// cp.async global->smem double buffering + register double-buffered fragments
// (LDS for kk+1 overlaps FFMA for kk). FFMA order per accumulator identical
// to prior passing kernels -> bitwise-identical results.
// AMODE 0: A[M,K] row-major (register-staged transpose into As[k][m]).
// AMODE 1: A[K,M]            (cp.async direct into As[k][m]).
// BMODE 0: B[K,N]            (cp.async direct into Bs[k][n]).
// BMODE 1: B[N,K]            (register-staged transpose into Bs[k][n]).
// C = scale*(A*B) + bias[row] + addbuf. ksplit: raw partials per z-slab.
template<int AMODE, int BMODE>
__global__ void __launch_bounds__(256, 2) sgemm_kernel(
    const float* __restrict__ A, const float* __restrict__ Bm, float* __restrict__ C,
    int Md, int Nd, int Kd,
    long long sA, long long sB, long long sC,
    const float* __restrict__ bias, const float* __restrict__ addbuf,
    float scale, int ksplit)
{
    __shared__ float As[2][16][128];
    __shared__ float Bs[2][16][128];
    int bz = blockIdx.z;
    int batch = bz / ksplit;
    int ks = bz - batch * ksplit;
    int kchunk = Kd / ksplit;
    int k0 = ks * kchunk;
    int ntiles = kchunk >> 4;
    const float* Ab = A + (long long)batch * sA;
    const float* Bb = Bm + (long long)batch * sB;
    float* Cb = C + (long long)bz * sC;
    int bm0 = blockIdx.y * 128;
    int bn0 = blockIdx.x * 128;
    int t = threadIdx.x;
    int row0 = (t >> 4) << 3;
    int col0 = (t & 15) << 3;

    uint32_t sAs = (uint32_t)__cvta_generic_to_shared(&As[0][0][0]);
    uint32_t sBs = (uint32_t)__cvta_generic_to_shared(&Bs[0][0][0]);

    float4 fa0, fa1, fb0, fb1;

    auto issueA = [&](int bb, int kt) {
        if (AMODE == 0) {
            int v0 = t, v1 = t + 256;
            fa0 = *reinterpret_cast<const float4*>(
                Ab + (long long)(bm0 + (v0 >> 2)) * Kd + kt + ((v0 & 3) << 2));
            fa1 = *reinterpret_cast<const float4*>(
                Ab + (long long)(bm0 + (v1 >> 2)) * Kd + kt + ((v1 & 3) << 2));
        } else {
#pragma unroll
            for (int i2 = 0; i2 < 2; ++i2) {
                int v = t + i2 * 256;
                int kk = v >> 5, mv = (v & 31) << 2;
                cp_async16(sAs + (uint32_t)((((bb << 11) | (kk << 7) | mv)) << 2),
                           Ab + (long long)(kt + kk) * Md + bm0 + mv);
            }
        }
    };
    auto storeA = [&](int bb) {
        if (AMODE == 0) {
            int v0 = t, r0 = v0 >> 2, k0v = (v0 & 3) << 2;
            As[bb][k0v + 0][r0] = fa0.x; As[bb][k0v + 1][r0] = fa0.y;
            As[bb][k0v + 2][r0] = fa0.z; As[bb][k0v + 3][r0] = fa0.w;
            int v1 = t + 256, r1 = v1 >> 2, k1v = (v1 & 3) << 2;
            As[bb][k1v + 0][r1] = fa1.x; As[bb][k1v + 1][r1] = fa1.y;
            As[bb][k1v + 2][r1] = fa1.z; As[bb][k1v + 3][r1] = fa1.w;
        }
    };
    auto issueB = [&](int bb, int kt) {
        if (BMODE == 0) {
#pragma unroll
            for (int i2 = 0; i2 < 2; ++i2) {
                int v = t + i2 * 256;
                int kk = v >> 5, nv = (v & 31) << 2;
                cp_async16(sBs + (uint32_t)((((bb << 11) | (kk << 7) | nv)) << 2),
                           Bb + (long long)(kt + kk) * Nd + bn0 + nv);
            }
        } else {
            int v0 = t, v1 = t + 256;
            fb0 = *reinterpret_cast<const float4*>(
                Bb + (long long)(bn0 + (v0 >> 2)) * Kd + kt + ((v0 & 3) << 2));
            fb1 = *reinterpret_cast<const float4*>(
                Bb + (long long)(bn0 + (v1 >> 2)) * Kd + kt + ((v1 & 3) << 2));
        }
    };
    auto storeB = [&](int bb) {
        if (BMODE == 1) {
            int v0 = t, n0 = v0 >> 2, k0v = (v0 & 3) << 2;
            Bs[bb][k0v + 0][n0] = fb0.x; Bs[bb][k0v + 1][n0] = fb0.y;
            Bs[bb][k0v + 2][n0] = fb0.z; Bs[bb][k0v + 3][n0] = fb0.w;
            int v1 = t + 256, n1 = v1 >> 2, k1v = (v1 & 3) << 2;
            Bs[bb][k1v + 0][n1] = fb1.x; Bs[bb][k1v + 1][n1] = fb1.y;
            Bs[bb][k1v + 2][n1] = fb1.z; Bs[bb][k1v + 3][n1] = fb1.w;
        }
    };

    float acc[8][8];
#pragma unroll
    for (int i = 0; i < 8; ++i)
#pragma unroll
        for (int j = 0; j < 8; ++j) acc[i][j] = 0.f;

    // prologue: stage tile 0 into buffer 0
    issueA(0, k0); issueB(0, k0);
    storeA(0); storeB(0);
    cp_commit();
    cp_wait_all();
    __syncthreads();

    float ra[2][8], rb[2][8];
    int buf = 0;
    for (int it = 0; it < ntiles; ++it) {
        bool hn = (it + 1 < ntiles);
        if (hn) {
            int ktn = k0 + ((it + 1) << 4);
            issueA(buf ^ 1, ktn);
            issueB(buf ^ 1, ktn);
            cp_commit();
        }
        const float (*Asb)[128] = As[buf];
        const float (*Bsb)[128] = Bs[buf];
        // fragment prologue (kk = 0)
        *reinterpret_cast<float4*>(&ra[0][0]) = *reinterpret_cast<const float4*>(&Asb[0][row0]);
        *reinterpret_cast<float4*>(&ra[0][4]) = *reinterpret_cast<const float4*>(&Asb[0][row0 + 4]);
        *reinterpret_cast<float4*>(&rb[0][0]) = *reinterpret_cast<const float4*>(&Bsb[0][col0]);
        *reinterpret_cast<float4*>(&rb[0][4]) = *reinterpret_cast<const float4*>(&Bsb[0][col0 + 4]);
#pragma unroll
        for (int kk = 0; kk < 16; ++kk) {
            int cur = kk & 1;
            int nxt = cur ^ 1;
            if (kk < 15) {
                *reinterpret_cast<float4*>(&ra[nxt][0]) =
                    *reinterpret_cast<const float4*>(&Asb[kk + 1][row0]);
                *reinterpret_cast<float4*>(&ra[nxt][4]) =
                    *reinterpret_cast<const float4*>(&Asb[kk + 1][row0 + 4]);
                *reinterpret_cast<float4*>(&rb[nxt][0]) =
                    *reinterpret_cast<const float4*>(&Bsb[kk + 1][col0]);
                *reinterpret_cast<float4*>(&rb[nxt][4]) =
                    *reinterpret_cast<const float4*>(&Bsb[kk + 1][col0 + 4]);
            }
#pragma unroll
            for (int i = 0; i < 8; ++i)
#pragma unroll
                for (int j = 0; j < 8; ++j)
                    acc[i][j] = fmaf(ra[cur][i], rb[cur][j], acc[i][j]);
        }
        if (hn) {
            storeA(buf ^ 1);
            storeB(buf ^ 1);
            cp_wait_all();
            __syncthreads();
            buf ^= 1;
        }
    }

#pragma unroll
    for (int i = 0; i < 8; ++i) {
        int r = bm0 + row0 + i;
        float bv = bias ? bias[r] : 0.f;
#pragma unroll
        for (int jv = 0; jv < 2; ++jv) {
            int cidx = bn0 + col0 + (jv << 2);
            float4 o;
            o.x = acc[i][jv * 4 + 0] * scale + bv;
            o.y = acc[i][jv * 4 + 1] * scale + bv;
            o.z = acc[i][jv * 4 + 2] * scale + bv;
            o.w = acc[i][jv * 4 + 3] * scale + bv;
            if (addbuf) {
                const float4 a4 = *reinterpret_cast<const float4*>(
                    addbuf + (long long)batch * sC + (long long)r * Nd + cidx);
                o.x += a4.x; o.y += a4.y; o.z += a4.z; o.w += a4.w;
            }
            *reinterpret_cast<float4*>(Cb + (long long)r * Nd + cidx) = o;
        }
    }
}

// ---------------- BatchNorm (train-mode) per-channel affine -----------------
__global__ void __launch_bounds__(256) bn_stats_kernel(
    const float* __restrict__ x, const float* __restrict__ gamma,
    const float* __restrict__ beta, float* __restrict__ scale,
    float* __restrict__ shift, int Cd)
{
    __shared__ float rs[8], rq[8];
    int c = blockIdx.x;
    int t = threadIdx.x;
    float s = 0.f, q = 0.f;
    for (int b = 0; b < BATCH; ++b) {
        const float4* p = reinterpret_cast<const float4*>(x + ((long long)b * Cd + c) * NPTS);
        for (int v = t; v < NPTS / 4; v += 256) {
            float4 f = p[v];
            s += f.x + f.y + f.z + f.w;
            q += f.x * f.x + f.y * f.y + f.z * f.z + f.w * f.w;
        }
    }
#pragma unroll
    for (int o = 16; o; o >>= 1) {
        s += __shfl_xor_sync(0xFFFFFFFFu, s, o);
        q += __shfl_xor_sync(0xFFFFFFFFu, q, o);
    }
    if ((t & 31) == 0) { rs[t >> 5] = s; rq[t >> 5] = q; }
    __syncthreads();
    if (t == 0) {
        float S = 0.f, Q = 0.f;
#pragma unroll
        for (int w = 0; w < 8; ++w) { S += rs[w]; Q += rq[w]; }
        const float inv = 1.f / (float)(BATCH * NPTS);
        float mean = S * inv;
        float var = Q * inv - mean * mean;
        float rstd = rsqrtf(var + 1e-5f);
        float g = gamma[c];
        scale[c] = rstd * g;
        shift[c] = beta[c] - mean * rstd * g;
    }
}

// ---------------- BN affine + LeakyReLU, in-place ---------------------------
__global__ void __launch_bounds__(256) bn_apply_kernel(
    float* __restrict__ x, const float* __restrict__ scale,
    const float* __restrict__ shift, int Cd)
{
    int total = BATCH * Cd * (NPTS / 4);
    for (int v = blockIdx.x * blockDim.x + threadIdx.x; v < total; v += gridDim.x * blockDim.x) {
        int c = (v >> 11) % Cd;     // 2048 float4 per channel row
        float s = scale[c], sh = shift[c];
        float4 f = reinterpret_cast<float4*>(x)[v];
        f.x = f.x * s + sh; f.y = f.y * s + sh;
        f.z = f.z * s + sh; f.w = f.w * s + sh;
        f.x = f.x > 0.f ? f.x : 0.2f * f.x;
        f.y = f.y > 0.f ? f.y : 0.2f * f.y;
        f.z = f.z > 0.f ? f.z : 0.2f * f.z;
        f.w = f.w > 0.f ? f.w : 0.2f * f.w;
        reinterpret_cast<float4*>(x)[v] = f;
    }
}

// ---------------- gather centroids (feat) and new_xyz -----------------------
__global__ void __launch_bounds__(256) gather_kernel(
    const float* __restrict__ xyz, float* __restrict__ out_xyz)
{
    int v = blockIdx.x * blockDim.x + threadIdx.x;
    if (v < BATCH * 256 * NCENT) {
        int b = v >> 17;
        int rem = v & 131071;
        int c = rem >> 9;
        int m = rem & 511;
        int id = g_idx[b * NCENT + m];
        g_cent[v] = g_feat[((long long)b * 256 + c) * NPTS + id];
    }
    if (v < BATCH * 3 * NCENT) {
        int b = v / (3 * NCENT);
        int rem = v - b * 3 * NCENT;
        int c = rem >> 9;
        int m = rem & 511;
        int id = g_idx[b * NCENT + m];
        out_xyz[v] = xyz[((long long)b * 3 + c) * NPTS + id];
    }
}

// ---------------- softmax over last dim, rows in registers ------------------
__global__ void __launch_bounds__(256) softmax_kernel()
{
    __shared__ float red[8];
    long long row = blockIdx.x;
    float4* p = reinterpret_cast<float4*>(g_logits + row * NPTS);
    int t = threadIdx.x;
    float4 v[8];
#pragma unroll
    for (int i = 0; i < 8; ++i) v[i] = p[t + (i << 8)];
    float mx = -1e30f;
#pragma unroll
    for (int i = 0; i < 8; ++i)
        mx = fmaxf(mx, fmaxf(fmaxf(v[i].x, v[i].y), fmaxf(v[i].z, v[i].w)));
#pragma unroll
    for (int o = 16; o; o >>= 1) mx = fmaxf(mx, __shfl_xor_sync(0xFFFFFFFFu, mx, o));
    if ((t & 31) == 0) red[t >> 5] = mx;
    __syncthreads();
#pragma unroll
    for (int w = 0; w < 8; ++w) mx = fmaxf(mx, red[w]);
    __syncthreads();
    float s = 0.f;
#pragma unroll
    for (int i = 0; i < 8; ++i) {
        v[i].x = __expf(v[i].x - mx); v[i].y = __expf(v[i].y - mx);
        v[i].z = __expf(v[i].z - mx); v[i].w = __expf(v[i].w - mx);
        s += v[i].x + v[i].y + v[i].z + v[i].w;
    }
#pragma unroll
    for (int o = 16; o; o >>= 1) s += __shfl_xor_sync(0xFFFFFFFFu, s, o);
    if ((t & 31) == 0) red[t >> 5] = s;
    __syncthreads();
    s = 0.f;
#pragma unroll
    for (int w = 0; w < 8; ++w) s += red[w];
    float inv = 1.f / s;
#pragma unroll
    for (int i = 0; i < 8; ++i) {
        v[i].x *= inv; v[i].y *= inv; v[i].z *= inv; v[i].w *= inv;
        p[t + (i << 8)] = v[i];
    }
}

// ---------------- split-K reduction (KSPLIT_PV slabs) -----------------------
__global__ void __launch_bounds__(256) reduceK_kernel()
{
    int v = blockIdx.x * blockDim.x + threadIdx.x;   // float4 index
    int total = BATCH * 256 * NCENT / 4;             // 262144
    if (v >= total) return;
    int b = v >> 15;                                  // 32768 f4 per batch
    int i = v & 32767;
    const float4* pp = reinterpret_cast<const float4*>(g_attpart);
    float4 s = pp[((long long)b * KSPLIT_PV + 0) * 32768 + i];
#pragma unroll
    for (int ks = 1; ks < KSPLIT_PV; ++ks) {
        float4 x = pp[((long long)b * KSPLIT_PV + ks) * 32768 + i];
        s.x += x.x; s.y += x.y; s.z += x.z; s.w += x.w;
    }
    reinterpret_cast<float4*>(g_att)[v] = s;
}

// ---------------- host launcher ---------------------------------------------
static float* sym(const void* s) {
    void* p = nullptr;
    cudaGetSymbolAddress(&p, (const void*)s);
    return (float*)p;
}

extern "C" void kernel_launch(void* const* d_in, const int* in_sizes, int n_in,
                              void* d_out, int out_size)
{
    const float* xyz = (const float*)d_in[0];
    const float* pf  = (const float*)d_in[1];
    const float* w1  = (const float*)d_in[2];
    const float* b1  = (const float*)d_in[3];
    const float* g1  = (const float*)d_in[4];
    const float* be1 = (const float*)d_in[5];
    const float* w2  = (const float*)d_in[6];
    const float* b2  = (const float*)d_in[7];
    const float* g2  = (const float*)d_in[8];
    const float* be2 = (const float*)d_in[9];
    const float* w3  = (const float*)d_in[10];
    const float* b3  = (const float*)d_in[11];
    const float* wq  = (const float*)d_in[12];
    const float* wk  = (const float*)d_in[13];
    const float* wv  = (const float*)d_in[14];
    const float* wo  = (const float*)d_in[15];
    const int*   far0 = (const int*)d_in[16];
    float* out = (float*)d_out;

    float* p_sup  = sym(g_support);
    float* p_h1   = sym(g_h1);
    float* p_h2   = sym(g_h2);
    float* p_feat = sym(g_feat);
    float* p_k    = sym(g_kbuf);
    float* p_v    = sym(g_vbuf);
    float* p_q    = sym(g_qbuf);
    float* p_cent = sym(g_cent);
    float* p_log  = sym(g_logits);
    float* p_ap   = sym(g_attpart);
    float* p_att  = sym(g_att);
    float* p_s1   = sym(g_bns1);
    float* p_sh1  = sym(g_bnh1);
    float* p_s2   = sym(g_bns2);
    float* p_sh2  = sym(g_bnh2);

    // 0. reset FPS coordination state (device globals persist across replays)
    fps_init_kernel<<<1, 64>>>();

    // 1. support = concat(xyz, point_features)
    support_kernel<<<1024, 256>>>(xyz, pf);

    // 2. FPS: 128 persistent CTAs (16 per batch), gmem barriers
    fps_kernel<<<128, 512>>>(far0);

    // 3. h1 = w1 @ support + b1
    sgemm_kernel<0, 0><<<dim3(64, 1, 8), 256>>>(
        w1, p_sup, p_h1, 128, NPTS, 64,
        0LL, 64LL * NPTS, 128LL * NPTS,
        b1, nullptr, 1.f, 1);

    // 4. BN1 stats + apply (in-place lrelu(bn(h1)))
    bn_stats_kernel<<<128, 256>>>(p_h1, g1, be1, p_s1, p_sh1, 128);
    bn_apply_kernel<<<2048, 256>>>(p_h1, p_s1, p_sh1, 128);

    // 5. h2 = w2 @ h1' + b2
    sgemm_kernel<0, 0><<<dim3(64, 2, 8), 256>>>(
        w2, p_h1, p_h2, 256, NPTS, 128,
        0LL, 128LL * NPTS, 256LL * NPTS,
        b2, nullptr, 1.f, 1);

    // 6. BN2 stats + apply
    bn_stats_kernel<<<256, 256>>>(p_h2, g2, be2, p_s2, p_sh2, 256);
    bn_apply_kernel<<<4096, 256>>>(p_h2, p_s2, p_sh2, 256);

    // 7. feat = w3 @ h2' + b3
    sgemm_kernel<0, 0><<<dim3(64, 2, 8), 256>>>(
        w3, p_h2, p_feat, 256, NPTS, 256,
        0LL, 256LL * NPTS, 256LL * NPTS,
        b3, nullptr, 1.f, 1);

    // 8. gather centroids + new_xyz (new_xyz = first 12288 floats of out)
    gather_kernel<<<4096, 256>>>(xyz, out);

    // 9/10. k = wk @ feat ; v = wv @ feat
    sgemm_kernel<0, 0><<<dim3(64, 2, 8), 256>>>(
        wk, p_feat, p_k, 256, NPTS, 256,
        0LL, 256LL * NPTS, 256LL * NPTS,
        nullptr, nullptr, 1.f, 1);
    sgemm_kernel<0, 0><<<dim3(64, 2, 8), 256>>>(
        wv, p_feat, p_v, 256, NPTS, 256,
        0LL, 256LL * NPTS, 256LL * NPTS,
        nullptr, nullptr, 1.f, 1);

    // 11. q = wq @ centroids
    sgemm_kernel<0, 0><<<dim3(4, 2, 8), 256>>>(
        wq, p_cent, p_q, 256, NCENT, 256,
        0LL, 256LL * NCENT, 256LL * NCENT,
        nullptr, nullptr, 1.f, 1);

    // 12. logits = (q^T k) / 16
    sgemm_kernel<1, 0><<<dim3(64, 4, 8), 256>>>(
        p_q, p_k, p_log, NCENT, NPTS, 256,
        256LL * NCENT, 256LL * NPTS, (long long)NCENT * NPTS,
        nullptr, nullptr, 0.0625f, 1);

    // 13. softmax over N
    softmax_kernel<<<BATCH * NCENT, 256>>>();

    // 14. att1 = probs @ v^T  (split-K)
    sgemm_kernel<0, 1><<<dim3(4, 2, 8 * KSPLIT_PV), 256>>>(
        p_v, p_log, p_ap, 256, NCENT, NPTS,
        256LL * NPTS, (long long)NCENT * NPTS, 256LL * NCENT,
        nullptr, nullptr, 1.f, KSPLIT_PV);

    // 15. reduce split-K partials
    reduceK_kernel<<<1024, 256>>>();

    // 16. out2 = centroids + wo @ att1 (written into out + 12288)
    sgemm_kernel<0, 0><<<dim3(4, 2, 8), 256>>>(
        wo, p_att, out + BATCH * 3 * NCENT, 256, NCENT, 256,
        0LL, 256LL * NCENT, 256LL * NCENT,
        nullptr, p_cent, 1.f, 1);
}

// round 13
// speedup vs baseline: 1.0842x; 1.0817x over previous
#include <cuda_runtime.h>
#include <cuda_bf16.h>
#include <mma.h>
#include <cstdint>

using namespace nvcuda;

#define BATCH 8
#define NPTS  8192
#define NCENT 512
#define KSPLIT_PV 8

// ---------------- fp32 scratch ----------------------------------------------
__device__ float g_support[BATCH * 64 * NPTS];
__device__ float g_h1[BATCH * 128 * NPTS];
__device__ float g_h2[BATCH * 256 * NPTS];
__device__ float g_feat[BATCH * 256 * NPTS];
__device__ float g_kbuf[BATCH * 256 * NPTS];
__device__ float g_vbuf[BATCH * 256 * NPTS];
__device__ float g_qbuf[BATCH * 256 * NCENT];
__device__ float g_cent[BATCH * 256 * NCENT];
__device__ float g_logits[BATCH * NCENT * NPTS];
__device__ float g_attpart[BATCH * KSPLIT_PV * 256 * NCENT];
__device__ float g_att[BATCH * 256 * NCENT];
__device__ int   g_idx[BATCH * NCENT];
__device__ float g_bns1[128], g_bnh1[128];
__device__ float g_bns2[256], g_bnh2[256];
__device__ unsigned long long g_best[BATCH * 8];
__device__ unsigned int       g_count[BATCH * 2];

// ---------------- bf16 split buffers (hi/lo) --------------------------------
__device__ __nv_bfloat16 g_w2h[256*128],  g_w2l[256*128];
__device__ __nv_bfloat16 g_w3h[256*256],  g_w3l[256*256];
__device__ __nv_bfloat16 g_wkh[256*256],  g_wkl[256*256];
__device__ __nv_bfloat16 g_wvh[256*256],  g_wvl[256*256];
__device__ __nv_bfloat16 g_h1Th[BATCH*NPTS*128], g_h1Tl[BATCH*NPTS*128];
__device__ __nv_bfloat16 g_h2Th[BATCH*NPTS*256], g_h2Tl[BATCH*NPTS*256];
__device__ __nv_bfloat16 g_fTh[BATCH*NPTS*256],  g_fTl[BATCH*NPTS*256];
__device__ __nv_bfloat16 g_kTh[BATCH*NPTS*256],  g_kTl[BATCH*NPTS*256];
__device__ __nv_bfloat16 g_vh[BATCH*256*NPTS],   g_vl[BATCH*256*NPTS];
__device__ __nv_bfloat16 g_qTh[BATCH*NCENT*256], g_qTl[BATCH*NCENT*256];
__device__ __nv_bfloat16 g_ph[BATCH*NCENT*NPTS], g_pl[BATCH*NCENT*NPTS];

// ---------------- helpers ----------------------------------------------------
__device__ __forceinline__ void cp_async16(uint32_t dst, const void* src) {
    asm volatile("cp.async.cg.shared.global [%0], [%1], 16;\n" :: "r"(dst), "l"(src));
}
__device__ __forceinline__ void cp_commit() { asm volatile("cp.async.commit_group;\n"); }
__device__ __forceinline__ void cp_wait_all() { asm volatile("cp.async.wait_group 0;\n" ::: "memory"); }

// ---------------- init / support / FPS (proven) ------------------------------
__global__ void fps_init_kernel()
{
    int t = threadIdx.x;
    if (t < BATCH * 8) g_best[t] = 0ull;
    if (t < BATCH * 2) g_count[t] = 0u;
}

__global__ void __launch_bounds__(256) support_kernel(
    const float* __restrict__ xyz, const float* __restrict__ pf)
{
    int total = BATCH * 64 * (NPTS / 4);
    for (int v = blockIdx.x * blockDim.x + threadIdx.x; v < total; v += gridDim.x * blockDim.x) {
        int b = v >> 17, rem = v & 131071, c = rem >> 11, nv = rem & 2047;
        float4 f;
        if (c < 3) f = reinterpret_cast<const float4*>(xyz + ((long long)b * 3 + c) * NPTS)[nv];
        else       f = reinterpret_cast<const float4*>(pf + ((long long)b * 61 + (c - 3)) * NPTS)[nv];
        reinterpret_cast<float4*>(g_support)[v] = f;
    }
}

__global__ void __launch_bounds__(512, 1) fps_kernel(const int* __restrict__ far0)
{
    __shared__ float cent[64];
    __shared__ unsigned long long warp_best[16];
    __shared__ int s_far;
    int rank = blockIdx.x & 15, b = blockIdx.x >> 4, t = threadIdx.x;
    const float* sb = g_support + (long long)b * 64 * NPTS;
    int myn = (rank << 9) + t;
    float p[64];
#pragma unroll
    for (int c = 0; c < 64; ++c) p[c] = sb[(c << 13) + myn];
    float distance = 1e10f;
    int far = far0[b];
    if (rank == 0 && t == 0) g_idx[b * NCENT] = far;
    unsigned long long* best = g_best + b * 8;
    volatile unsigned int* cnt = (volatile unsigned int*)(g_count + b * 2);
    for (int m = 0; m < NCENT - 1; ++m) {
        if (t < 64) cent[t] = sb[(t << 13) + far];
        __syncthreads();
        double dd = 0.0;
#pragma unroll
        for (int c = 0; c < 64; ++c) {
            double df = (double)p[c] - (double)cent[c];
            dd = fma(df, df, dd);
        }
        float d = (float)dd;
        distance = fminf(distance, d);
        unsigned long long key = ((unsigned long long)__float_as_uint(distance) << 32)
                               | (unsigned long long)(0xFFFFFFFFu - (unsigned)myn);
#pragma unroll
        for (int o = 16; o > 0; o >>= 1) {
            unsigned long long ok = __shfl_xor_sync(0xFFFFFFFFu, key, o);
            key = (ok > key) ? ok : key;
        }
        if ((t & 31) == 0) warp_best[t >> 5] = key;
        __syncthreads();
        if (t == 0) {
            unsigned long long kk = warp_best[0];
#pragma unroll
            for (int w = 1; w < 16; ++w) { unsigned long long o2 = warp_best[w]; kk = (o2 > kk) ? o2 : kk; }
            int slot = m & 7, par = m & 1;
            atomicMax(best + slot, kk);
            __threadfence();
            atomicAdd((unsigned int*)(g_count + b * 2 + par), 1u);
            unsigned target = 16u * (unsigned)(m / 2 + 1);
            while (cnt[par] < target) { }
            __threadfence();
            unsigned long long win = best[slot];
            int f = (int)(0xFFFFFFFFu - (unsigned)(win & 0xFFFFFFFFull));
            s_far = f;
            if (rank == 0) { g_idx[b * NCENT + m + 1] = f; best[(m + 4) & 7] = 0ull; }
        }
        __syncthreads();
        far = s_far;
    }
}

// ---------------- fp32 SGEMM (h1/q/wo; proven) -------------------------------
__global__ void __launch_bounds__(256, 2) sgemm_kernel(
    const float* __restrict__ A, const float* __restrict__ Bm, float* __restrict__ C,
    int Nd, int Kd, long long sB, long long sC,
    const float* __restrict__ bias, const float* __restrict__ addbuf, float scale)
{
    __shared__ float As[2][16][128];
    __shared__ float Bs[2][16][128];
    int batch = blockIdx.z;
    const float* Bb = Bm + (long long)batch * sB;
    float* Cb = C + (long long)batch * sC;
    int bm0 = blockIdx.y * 128, bn0 = blockIdx.x * 128;
    int t = threadIdx.x, row0 = (t >> 4) << 3, col0 = (t & 15) << 3;
    int ntiles = Kd >> 4;
    uint32_t sBs = (uint32_t)__cvta_generic_to_shared(&Bs[0][0][0]);
    float4 fa0, fa1;
    auto issueA = [&](int kt) {
        fa0 = *reinterpret_cast<const float4*>(A + (long long)(bm0 + (t >> 2)) * Kd + kt + ((t & 3) << 2));
        int v1 = t + 256;
        fa1 = *reinterpret_cast<const float4*>(A + (long long)(bm0 + (v1 >> 2)) * Kd + kt + ((v1 & 3) << 2));
    };
    auto storeA = [&](int bb) {
        int r0 = t >> 2, k0v = (t & 3) << 2;
        As[bb][k0v + 0][r0] = fa0.x; As[bb][k0v + 1][r0] = fa0.y;
        As[bb][k0v + 2][r0] = fa0.z; As[bb][k0v + 3][r0] = fa0.w;
        int v1 = t + 256, r1 = v1 >> 2, k1v = (v1 & 3) << 2;
        As[bb][k1v + 0][r1] = fa1.x; As[bb][k1v + 1][r1] = fa1.y;
        As[bb][k1v + 2][r1] = fa1.z; As[bb][k1v + 3][r1] = fa1.w;
    };
    auto issueB = [&](int bb, int kt) {
#pragma unroll
        for (int i2 = 0; i2 < 2; ++i2) {
            int v = t + i2 * 256, kk = v >> 5, nv = (v & 31) << 2;
            cp_async16(sBs + (uint32_t)((((bb << 11) | (kk << 7) | nv)) << 2),
                       Bb + (long long)(kt + kk) * Nd + bn0 + nv);
        }
    };
    float acc[8][8];
#pragma unroll
    for (int i = 0; i < 8; ++i)
#pragma unroll
        for (int j = 0; j < 8; ++j) acc[i][j] = 0.f;
    issueA(0); issueB(0, 0); storeA(0);
    cp_commit(); cp_wait_all();
    __syncthreads();
    int buf = 0;
    for (int it = 0; it < ntiles; ++it) {
        bool hn = (it + 1 < ntiles);
        if (hn) { issueA((it + 1) << 4); issueB(buf ^ 1, (it + 1) << 4); cp_commit(); }
        const float (*Asb)[128] = As[buf];
        const float (*Bsb)[128] = Bs[buf];
#pragma unroll
        for (int kk = 0; kk < 16; ++kk) {
            float ra[8], rb[8];
            *reinterpret_cast<float4*>(&ra[0]) = *reinterpret_cast<const float4*>(&Asb[kk][row0]);
            *reinterpret_cast<float4*>(&ra[4]) = *reinterpret_cast<const float4*>(&Asb[kk][row0 + 4]);
            *reinterpret_cast<float4*>(&rb[0]) = *reinterpret_cast<const float4*>(&Bsb[kk][col0]);
            *reinterpret_cast<float4*>(&rb[4]) = *reinterpret_cast<const float4*>(&Bsb[kk][col0 + 4]);
#pragma unroll
            for (int i = 0; i < 8; ++i)
#pragma unroll
                for (int j = 0; j < 8; ++j) acc[i][j] = fmaf(ra[i], rb[j], acc[i][j]);
        }
        if (hn) { storeA(buf ^ 1); cp_wait_all(); __syncthreads(); buf ^= 1; }
    }
#pragma unroll
    for (int i = 0; i < 8; ++i) {
        int r = bm0 + row0 + i;
        float bv = bias ? bias[r] : 0.f;
#pragma unroll
        for (int jv = 0; jv < 2; ++jv) {
            int cidx = bn0 + col0 + (jv << 2);
            float4 o;
            o.x = acc[i][jv * 4 + 0] * scale + bv; o.y = acc[i][jv * 4 + 1] * scale + bv;
            o.z = acc[i][jv * 4 + 2] * scale + bv; o.w = acc[i][jv * 4 + 3] * scale + bv;
            if (addbuf) {
                const float4 a4 = *reinterpret_cast<const float4*>(
                    addbuf + (long long)batch * sC + (long long)r * Nd + cidx);
                o.x += a4.x; o.y += a4.y; o.z += a4.z; o.w += a4.w;
            }
            *reinterpret_cast<float4*>(Cb + (long long)r * Nd + cidx) = o;
        }
    }
}

// ---------------- WMMA bf16-split GEMM: C = scale*(A @ B^T) ------------------
// A[M,K], B[N,K] K-major bf16 (hi/lo). 128x128 CTA tile, 8 warps (4x2),
// warp computes 32x64 via 2x4 m16n16k16 fragments. 3 terms: hh + hl + lh.
__global__ void __launch_bounds__(256) tc_gemm_kernel(
    const __nv_bfloat16* __restrict__ Ahg, const __nv_bfloat16* __restrict__ Alg,
    const __nv_bfloat16* __restrict__ Bhg, const __nv_bfloat16* __restrict__ Blg,
    float* __restrict__ C, int Nd, int Kd,
    long long sA, long long sB, long long sC,
    float scale, int ksplit)
{
    __shared__ __align__(128) __nv_bfloat16 sm[4][128][32];
    int t = threadIdx.x, wid = t >> 5;
    int bz = blockIdx.z, batch = bz / ksplit, ks = bz - batch * ksplit;
    int kchunk = Kd / ksplit, k0 = ks * kchunk, niter = kchunk >> 4;
    int bm0 = blockIdx.y << 7, bn0 = blockIdx.x << 7;
    const __nv_bfloat16* src4[4];
    src4[0] = Ahg + (long long)batch * sA + (long long)bm0 * Kd;
    src4[1] = Alg + (long long)batch * sA + (long long)bm0 * Kd;
    src4[2] = Bhg + (long long)batch * sB + (long long)bn0 * Kd;
    src4[3] = Blg + (long long)batch * sB + (long long)bn0 * Kd;
    int wm = wid & 3, wn = wid >> 2;

    wmma::fragment<wmma::accumulator, 16, 16, 16, float> acc[2][4];
#pragma unroll
    for (int i = 0; i < 2; ++i)
#pragma unroll
        for (int j = 0; j < 4; ++j) wmma::fill_fragment(acc[i][j], 0.f);

    uint32_t sbase = (uint32_t)__cvta_generic_to_shared(&sm[0][0][0]);
    int lrow = t >> 1, lch = t & 1;

    for (int it = 0; it < niter; ++it) {
        int kt = k0 + (it << 4);
#pragma unroll
        for (int i = 0; i < 4; ++i) {
            cp_async16(sbase + (uint32_t)((i << 13) + (lrow << 6) + (lch << 4)),
                       src4[i] + (long long)lrow * Kd + kt + (lch << 3));
        }
        cp_commit(); cp_wait_all();
        __syncthreads();

        wmma::fragment<wmma::matrix_a, 16, 16, 16, __nv_bfloat16, wmma::row_major> ah[2], al[2];
#pragma unroll
        for (int mf = 0; mf < 2; ++mf) {
            int r = wm * 32 + mf * 16;
            wmma::load_matrix_sync(ah[mf], &sm[0][r][0], 32);
            wmma::load_matrix_sync(al[mf], &sm[1][r][0], 32);
        }
#pragma unroll
        for (int nf = 0; nf < 4; ++nf) {
            int n = wn * 64 + nf * 16;
            wmma::fragment<wmma::matrix_b, 16, 16, 16, __nv_bfloat16, wmma::col_major> bh, bl;
            wmma::load_matrix_sync(bh, &sm[2][n][0], 32);
            wmma::load_matrix_sync(bl, &sm[3][n][0], 32);
#pragma unroll
            for (int mf = 0; mf < 2; ++mf) {
                wmma::mma_sync(acc[mf][nf], ah[mf], bh, acc[mf][nf]);
                wmma::mma_sync(acc[mf][nf], ah[mf], bl, acc[mf][nf]);
                wmma::mma_sync(acc[mf][nf], al[mf], bh, acc[mf][nf]);
            }
        }
        __syncthreads();
    }

    float* Cb = C + (long long)bz * sC;
#pragma unroll
    for (int mf = 0; mf < 2; ++mf)
#pragma unroll
        for (int nf = 0; nf < 4; ++nf) {
#pragma unroll
            for (int e = 0; e < acc[mf][nf].num_elements; ++e) acc[mf][nf].x[e] *= scale;
            wmma::store_matrix_sync(
                Cb + (long long)(bm0 + wm * 32 + mf * 16) * Nd + bn0 + wn * 64 + nf * 16,
                acc[mf][nf], Nd, wmma::mem_row_major);
        }
}

// ---------------- converters --------------------------------------------------
__global__ void __launch_bounds__(256) split_kernel(
    const float* __restrict__ src, __nv_bfloat16* __restrict__ hi,
    __nv_bfloat16* __restrict__ lo, int total4)
{
    for (int v = blockIdx.x * blockDim.x + threadIdx.x; v < total4; v += gridDim.x * blockDim.x) {
        float4 f = reinterpret_cast<const float4*>(src)[v];
        __nv_bfloat16 h0 = __float2bfloat16(f.x), h1 = __float2bfloat16(f.y);
        __nv_bfloat16 h2 = __float2bfloat16(f.z), h3 = __float2bfloat16(f.w);
        __nv_bfloat162 a, b;
        a.x = h0; a.y = h1; b.x = h2; b.y = h3;
        reinterpret_cast<__nv_bfloat162*>(hi)[v * 2] = a;
        reinterpret_cast<__nv_bfloat162*>(hi)[v * 2 + 1] = b;
        a.x = __float2bfloat16(f.x - __bfloat162float(h0));
        a.y = __float2bfloat16(f.y - __bfloat162float(h1));
        b.x = __float2bfloat16(f.z - __bfloat162float(h2));
        b.y = __float2bfloat16(f.w - __bfloat162float(h3));
        reinterpret_cast<__nv_bfloat162*>(lo)[v * 2] = a;
        reinterpret_cast<__nv_bfloat162*>(lo)[v * 2 + 1] = b;
    }
}

// src [b][C][N] -> dst [b][N][C] bf16 split. grid(N/32, C/32, BATCH), 256 thr.
__global__ void __launch_bounds__(256) tsplit_kernel(
    const float* __restrict__ src, __nv_bfloat16* __restrict__ hi,
    __nv_bfloat16* __restrict__ lo, int C, int N)
{
    __shared__ float tile[32][33];
    int b = blockIdx.z, c0 = blockIdx.y * 32, n0 = blockIdx.x * 32;
    int tx = threadIdx.x & 31, ty = threadIdx.x >> 5;
    const float* s = src + (long long)b * C * N;
#pragma unroll
    for (int i = 0; i < 32; i += 8)
        tile[ty + i][tx] = s[(long long)(c0 + ty + i) * N + n0 + tx];
    __syncthreads();
    __nv_bfloat16* H = hi + ((long long)b * N + n0) * C + c0;
    __nv_bfloat16* L = lo + ((long long)b * N + n0) * C + c0;
#pragma unroll
    for (int i = 0; i < 32; i += 8) {
        float x = tile[tx][ty + i];
        __nv_bfloat16 h = __float2bfloat16(x);
        H[(long long)(ty + i) * C + tx] = h;
        L[(long long)(ty + i) * C + tx] = __float2bfloat16(x - __bfloat162float(h));
    }
}

// ---------------- BN / addbias / gather / softmax / reduce -------------------
__global__ void __launch_bounds__(256) bn_stats_kernel(
    const float* __restrict__ x, const float* __restrict__ gamma,
    const float* __restrict__ beta, float* __restrict__ scale,
    float* __restrict__ shift, int Cd)
{
    __shared__ float rs[8], rq[8];
    int c = blockIdx.x, t = threadIdx.x;
    float s = 0.f, q = 0.f;
    for (int b = 0; b < BATCH; ++b) {
        const float4* p = reinterpret_cast<const float4*>(x + ((long long)b * Cd + c) * NPTS);
        for (int v = t; v < NPTS / 4; v += 256) {
            float4 f = p[v];
            s += f.x + f.y + f.z + f.w;
            q += f.x * f.x + f.y * f.y + f.z * f.z + f.w * f.w;
        }
    }
#pragma unroll
    for (int o = 16; o; o >>= 1) {
        s += __shfl_xor_sync(0xFFFFFFFFu, s, o);
        q += __shfl_xor_sync(0xFFFFFFFFu, q, o);
    }
    if ((t & 31) == 0) { rs[t >> 5] = s; rq[t >> 5] = q; }
    __syncthreads();
    if (t == 0) {
        float S = 0.f, Q = 0.f;
#pragma unroll
        for (int w = 0; w < 8; ++w) { S += rs[w]; Q += rq[w]; }
        const float inv = 1.f / (float)(BATCH * NPTS);
        float mean = S * inv, var = Q * inv - mean * mean;
        float rstd = rsqrtf(var + 1e-5f), g = gamma[c];
        scale[c] = rstd * g;
        shift[c] = beta[c] - mean * rstd * g;
    }
}

__global__ void __launch_bounds__(256) bn_apply_kernel(
    float* __restrict__ x, const float* __restrict__ scale,
    const float* __restrict__ shift, int Cd)
{
    int total = BATCH * Cd * (NPTS / 4);
    for (int v = blockIdx.x * blockDim.x + threadIdx.x; v < total; v += gridDim.x * blockDim.x) {
        int c = (v >> 11) % Cd;
        float s = scale[c], sh = shift[c];
        float4 f = reinterpret_cast<float4*>(x)[v];
        f.x = f.x * s + sh; f.y = f.y * s + sh; f.z = f.z * s + sh; f.w = f.w * s + sh;
        f.x = f.x > 0.f ? f.x : 0.2f * f.x; f.y = f.y > 0.f ? f.y : 0.2f * f.y;
        f.z = f.z > 0.f ? f.z : 0.2f * f.z; f.w = f.w > 0.f ? f.w : 0.2f * f.w;
        reinterpret_cast<float4*>(x)[v] = f;
    }
}

__global__ void __launch_bounds__(256) addbias_kernel(
    float* __restrict__ x, const float* __restrict__ bias, int Cd)
{
    int total = BATCH * Cd * (NPTS / 4);
    for (int v = blockIdx.x * blockDim.x + threadIdx.x; v < total; v += gridDim.x * blockDim.x) {
        int c = (v >> 11) % Cd;
        float bv = bias[c];
        float4 f = reinterpret_cast<float4*>(x)[v];
        f.x += bv; f.y += bv; f.z += bv; f.w += bv;
        reinterpret_cast<float4*>(x)[v] = f;
    }
}

__global__ void __launch_bounds__(256) gather_kernel(
    const float* __restrict__ xyz, float* __restrict__ out_xyz)
{
    int v = blockIdx.x * blockDim.x + threadIdx.x;
    if (v < BATCH * 256 * NCENT) {
        int b = v >> 17, rem = v & 131071, c = rem >> 9, m = rem & 511;
        int id = g_idx[b * NCENT + m];
        g_cent[v] = g_feat[((long long)b * 256 + c) * NPTS + id];
    }
    if (v < BATCH * 3 * NCENT) {
        int b = v / (3 * NCENT), rem = v - b * 3 * NCENT, c = rem >> 9, m = rem & 511;
        int id = g_idx[b * NCENT + m];
        out_xyz[v] = xyz[((long long)b * 3 + c) * NPTS + id];
    }
}

__global__ void __launch_bounds__(256) softmax_kernel()
{
    __shared__ float red[8];
    long long row = blockIdx.x;
    float4* p = reinterpret_cast<float4*>(g_logits + row * NPTS);
    int t = threadIdx.x;
    float4 v[8];
#pragma unroll
    for (int i = 0; i < 8; ++i) v[i] = p[t + (i << 8)];
    float mx = -1e30f;
#pragma unroll
    for (int i = 0; i < 8; ++i)
        mx = fmaxf(mx, fmaxf(fmaxf(v[i].x, v[i].y), fmaxf(v[i].z, v[i].w)));
#pragma unroll
    for (int o = 16; o; o >>= 1) mx = fmaxf(mx, __shfl_xor_sync(0xFFFFFFFFu, mx, o));
    if ((t & 31) == 0) red[t >> 5] = mx;
    __syncthreads();
#pragma unroll
    for (int w = 0; w < 8; ++w) mx = fmaxf(mx, red[w]);
    __syncthreads();
    float s = 0.f;
#pragma unroll
    for (int i = 0; i < 8; ++i) {
        v[i].x = __expf(v[i].x - mx); v[i].y = __expf(v[i].y - mx);
        v[i].z = __expf(v[i].z - mx); v[i].w = __expf(v[i].w - mx);
        s += v[i].x + v[i].y + v[i].z + v[i].w;
    }
#pragma unroll
    for (int o = 16; o; o >>= 1) s += __shfl_xor_sync(0xFFFFFFFFu, s, o);
    if ((t & 31) == 0) red[t >> 5] = s;
    __syncthreads();
    s = 0.f;
#pragma unroll
    for (int w = 0; w < 8; ++w) s += red[w];
    float inv = 1.f / s;
#pragma unroll
    for (int i = 0; i < 8; ++i) {
        v[i].x *= inv; v[i].y *= inv; v[i].z *= inv; v[i].w *= inv;
        p[t + (i << 8)] = v[i];
    }
}

__global__ void __launch_bounds__(256) reduceK_kernel()
{
    int v = blockIdx.x * blockDim.x + threadIdx.x;
    int total = BATCH * 256 * NCENT / 4;
    if (v >= total) return;
    int b = v >> 15, i = v & 32767;
    const float4* pp = reinterpret_cast<const float4*>(g_attpart);
    float4 s = pp[((long long)b * KSPLIT_PV + 0) * 32768 + i];
#pragma unroll
    for (int ks = 1; ks < KSPLIT_PV; ++ks) {
        float4 x = pp[((long long)b * KSPLIT_PV + ks) * 32768 + i];
        s.x += x.x; s.y += x.y; s.z += x.z; s.w += x.w;
    }
    reinterpret_cast<float4*>(g_att)[v] = s;
}

// ---------------- host launcher ---------------------------------------------
static float* sym(const void* s) { void* p = nullptr; cudaGetSymbolAddress(&p, (const void*)s); return (float*)p; }
static __nv_bfloat16* symb(const void* s) { void* p = nullptr; cudaGetSymbolAddress(&p, (const void*)s); return (__nv_bfloat16*)p; }

extern "C" void kernel_launch(void* const* d_in, const int* in_sizes, int n_in,
                              void* d_out, int out_size)
{
    const float* xyz = (const float*)d_in[0];
    const float* pf  = (const float*)d_in[1];
    const float* w1  = (const float*)d_in[2];
    const float* b1  = (const float*)d_in[3];
    const float* g1  = (const float*)d_in[4];
    const float* be1 = (const float*)d_in[5];
    const float* w2  = (const float*)d_in[6];
    const float* g2  = (const float*)d_in[8];
    const float* be2 = (const float*)d_in[9];
    const float* w3  = (const float*)d_in[10];
    const float* b3  = (const float*)d_in[11];
    const float* wq  = (const float*)d_in[12];
    const float* wk  = (const float*)d_in[13];
    const float* wv  = (const float*)d_in[14];
    const float* wo  = (const float*)d_in[15];
    const int*   far0 = (const int*)d_in[16];
    float* out = (float*)d_out;

    float* p_sup = sym(g_support); float* p_h1 = sym(g_h1); float* p_h2 = sym(g_h2);
    float* p_feat = sym(g_feat); float* p_k = sym(g_kbuf); float* p_v = sym(g_vbuf);
    float* p_q = sym(g_qbuf); float* p_cent = sym(g_cent); float* p_log = sym(g_logits);
    float* p_ap = sym(g_attpart); float* p_att = sym(g_att);
    float* p_s1 = sym(g_bns1); float* p_sh1 = sym(g_bnh1);
    float* p_s2 = sym(g_bns2); float* p_sh2 = sym(g_bnh2);

    __nv_bfloat16 *w2h = symb(g_w2h), *w2l = symb(g_w2l), *w3h = symb(g_w3h), *w3l = symb(g_w3l);
    __nv_bfloat16 *wkh = symb(g_wkh), *wkl = symb(g_wkl), *wvh = symb(g_wvh), *wvl = symb(g_wvl);
    __nv_bfloat16 *h1Th = symb(g_h1Th), *h1Tl = symb(g_h1Tl), *h2Th = symb(g_h2Th), *h2Tl = symb(g_h2Tl);
    __nv_bfloat16 *fTh = symb(g_fTh), *fTl = symb(g_fTl), *kTh = symb(g_kTh), *kTl = symb(g_kTl);
    __nv_bfloat16 *vh = symb(g_vh), *vl = symb(g_vl), *qTh = symb(g_qTh), *qTl = symb(g_qTl);
    __nv_bfloat16 *ph = symb(g_ph), *pl = symb(g_pl);

    fps_init_kernel<<<1, 64>>>();
    support_kernel<<<1024, 256>>>(xyz, pf);
    fps_kernel<<<128, 512>>>(far0);

    // weight splits
    split_kernel<<<32, 256>>>(w2, w2h, w2l, 256 * 128 / 4);
    split_kernel<<<64, 256>>>(w3, w3h, w3l, 256 * 256 / 4);
    split_kernel<<<64, 256>>>(wk, wkh, wkl, 256 * 256 / 4);
    split_kernel<<<64, 256>>>(wv, wvh, wvl, 256 * 256 / 4);

    // h1 = w1 @ support + b1 (fp32), BN1, transpose-split
    sgemm_kernel<<<dim3(64, 1, 8), 256>>>(w1, p_sup, p_h1, NPTS, 64,
        64LL * NPTS, 128LL * NPTS, b1, nullptr, 1.f);
    bn_stats_kernel<<<128, 256>>>(p_h1, g1, be1, p_s1, p_sh1, 128);
    bn_apply_kernel<<<2048, 256>>>(p_h1, p_s1, p_sh1, 128);
    tsplit_kernel<<<dim3(256, 4, 8), 256>>>(p_h1, h1Th, h1Tl, 128, NPTS);

    // h2 = w2 @ h1' (tc; b2 cancels inside BN), BN2, transpose-split
    tc_gemm_kernel<<<dim3(64, 2, 8), 256>>>(w2h, w2l, h1Th, h1Tl, p_h2,
        NPTS, 128, 0LL, (long long)NPTS * 128, 256LL * NPTS, 1.f, 1);
    bn_stats_kernel<<<256, 256>>>(p_h2, g2, be2, p_s2, p_sh2, 256);
    bn_apply_kernel<<<4096, 256>>>(p_h2, p_s2, p_sh2, 256);
    tsplit_kernel<<<dim3(256, 8, 8), 256>>>(p_h2, h2Th, h2Tl, 256, NPTS);

    // feat = w3 @ h2' (tc) + b3
    tc_gemm_kernel<<<dim3(64, 2, 8), 256>>>(w3h, w3l, h2Th, h2Tl, p_feat,
        NPTS, 256, 0LL, (long long)NPTS * 256, 256LL * NPTS, 1.f, 1);
    addbias_kernel<<<4096, 256>>>(p_feat, b3, 256);
    gather_kernel<<<4096, 256>>>(xyz, out);
    tsplit_kernel<<<dim3(256, 8, 8), 256>>>(p_feat, fTh, fTl, 256, NPTS);

    // k, v (tc)
    tc_gemm_kernel<<<dim3(64, 2, 8), 256>>>(wkh, wkl, fTh, fTl, p_k,
        NPTS, 256, 0LL, (long long)NPTS * 256, 256LL * NPTS, 1.f, 1);
    tc_gemm_kernel<<<dim3(64, 2, 8), 256>>>(wvh, wvl, fTh, fTl, p_v,
        NPTS, 256, 0LL, (long long)NPTS * 256, 256LL * NPTS, 1.f, 1);
    tsplit_kernel<<<dim3(256, 8, 8), 256>>>(p_k, kTh, kTl, 256, NPTS);
    split_kernel<<<4096, 256>>>(p_v, vh, vl, BATCH * 256 * NPTS / 4);

    // q = wq @ centroids (fp32) then transpose-split
    sgemm_kernel<<<dim3(4, 2, 8), 256>>>(wq, p_cent, p_q, NCENT, 256,
        256LL * NCENT, 256LL * NCENT, nullptr, nullptr, 1.f);
    tsplit_kernel<<<dim3(16, 8, 8), 256>>>(p_q, qTh, qTl, 256, NCENT);

    // logits = (q^T k) / 16 (tc)
    tc_gemm_kernel<<<dim3(64, 4, 8), 256>>>(qTh, qTl, kTh, kTl, p_log,
        NPTS, 256, (long long)NCENT * 256, (long long)NPTS * 256,
        (long long)NCENT * NPTS, 0.0625f, 1);

    softmax_kernel<<<BATCH * NCENT, 256>>>();
    split_kernel<<<4096, 256>>>(p_log, ph, pl, BATCH * NCENT * NPTS / 4);

    // att = probs @ v^T (tc, split-K 8)
    tc_gemm_kernel<<<dim3(4, 2, 8 * KSPLIT_PV), 256>>>(vh, vl, ph, pl, p_ap,
        NCENT, NPTS, 256LL * NPTS, (long long)NCENT * NPTS, 256LL * NCENT,
        1.f, KSPLIT_PV);
    reduceK_kernel<<<1024, 256>>>();

    // out2 = centroids + wo @ att (fp32)
    sgemm_kernel<<<dim3(4, 2, 8), 256>>>(wo, p_att, out + BATCH * 3 * NCENT, NCENT, 256,
        256LL * NCENT, 256LL * NCENT, nullptr, p_cent, 1.f);
}

// round 14
// speedup vs baseline: 1.1905x; 1.0980x over previous
#include <cuda_runtime.h>
#include <cuda_bf16.h>
#include <mma.h>
#include <cstdint>

using namespace nvcuda;

#define BATCH 8
#define NPTS  8192
#define NCENT 512
#define KSPLIT_PV 8

// ---------------- fp32 scratch ----------------------------------------------
__device__ float g_support[BATCH * 64 * NPTS];
__device__ float g_h1[BATCH * 128 * NPTS];
__device__ float g_h2[BATCH * 256 * NPTS];
__device__ float g_feat[BATCH * 256 * NPTS];
__device__ float g_kbuf[BATCH * 256 * NPTS];
__device__ float g_vbuf[BATCH * 256 * NPTS];
__device__ float g_qbuf[BATCH * 256 * NCENT];
__device__ float g_cent[BATCH * 256 * NCENT];
__device__ float g_logits[BATCH * NCENT * NPTS];
__device__ float g_attpart[BATCH * KSPLIT_PV * 256 * NCENT];
__device__ float g_att[BATCH * 256 * NCENT];
__device__ int   g_idx[BATCH * NCENT];
__device__ float g_bns1[128], g_bnh1[128];
__device__ float g_bns2[256], g_bnh2[256];
__device__ unsigned long long g_best[BATCH * 8];
__device__ unsigned int       g_count[BATCH * 2];

// ---------------- bf16 split buffers (hi/lo) --------------------------------
__device__ __nv_bfloat16 g_w2h[256*128],  g_w2l[256*128];
__device__ __nv_bfloat16 g_w3h[256*256],  g_w3l[256*256];
__device__ __nv_bfloat16 g_wkh[256*256],  g_wkl[256*256];
__device__ __nv_bfloat16 g_wvh[256*256],  g_wvl[256*256];
__device__ __nv_bfloat16 g_h1Th[BATCH*NPTS*128], g_h1Tl[BATCH*NPTS*128];
__device__ __nv_bfloat16 g_h2Th[BATCH*NPTS*256], g_h2Tl[BATCH*NPTS*256];
__device__ __nv_bfloat16 g_fTh[BATCH*NPTS*256],  g_fTl[BATCH*NPTS*256];
__device__ __nv_bfloat16 g_kTh[BATCH*NPTS*256],  g_kTl[BATCH*NPTS*256];
__device__ __nv_bfloat16 g_vh[BATCH*256*NPTS],   g_vl[BATCH*256*NPTS];
__device__ __nv_bfloat16 g_qTh[BATCH*NCENT*256], g_qTl[BATCH*NCENT*256];
__device__ __nv_bfloat16 g_ph[BATCH*NCENT*NPTS], g_pl[BATCH*NCENT*NPTS];

// ---------------- helpers ----------------------------------------------------
__device__ __forceinline__ void cp_async16(uint32_t dst, const void* src) {
    asm volatile("cp.async.cg.shared.global [%0], [%1], 16;\n" :: "r"(dst), "l"(src));
}
__device__ __forceinline__ void cp_commit() { asm volatile("cp.async.commit_group;\n"); }
__device__ __forceinline__ void cp_wait_all() { asm volatile("cp.async.wait_group 0;\n" ::: "memory"); }
__device__ __forceinline__ void cp_wait1() { asm volatile("cp.async.wait_group 1;\n" ::: "memory"); }

// ---------------- init / support / FPS (proven) ------------------------------
__global__ void fps_init_kernel()
{
    int t = threadIdx.x;
    if (t < BATCH * 8) g_best[t] = 0ull;
    if (t < BATCH * 2) g_count[t] = 0u;
}

__global__ void __launch_bounds__(256) support_kernel(
    const float* __restrict__ xyz, const float* __restrict__ pf)
{
    int total = BATCH * 64 * (NPTS / 4);
    for (int v = blockIdx.x * blockDim.x + threadIdx.x; v < total; v += gridDim.x * blockDim.x) {
        int b = v >> 17, rem = v & 131071, c = rem >> 11, nv = rem & 2047;
        float4 f;
        if (c < 3) f = reinterpret_cast<const float4*>(xyz + ((long long)b * 3 + c) * NPTS)[nv];
        else       f = reinterpret_cast<const float4*>(pf + ((long long)b * 61 + (c - 3)) * NPTS)[nv];
        reinterpret_cast<float4*>(g_support)[v] = f;
    }
}

__global__ void __launch_bounds__(512, 1) fps_kernel(const int* __restrict__ far0)
{
    __shared__ float cent[64];
    __shared__ unsigned long long warp_best[16];
    __shared__ int s_far;
    int rank = blockIdx.x & 15, b = blockIdx.x >> 4, t = threadIdx.x;
    const float* sb = g_support + (long long)b * 64 * NPTS;
    int myn = (rank << 9) + t;
    float p[64];
#pragma unroll
    for (int c = 0; c < 64; ++c) p[c] = sb[(c << 13) + myn];
    float distance = 1e10f;
    int far = far0[b];
    if (rank == 0 && t == 0) g_idx[b * NCENT] = far;
    unsigned long long* best = g_best + b * 8;
    volatile unsigned int* cnt = (volatile unsigned int*)(g_count + b * 2);
    for (int m = 0; m < NCENT - 1; ++m) {
        if (t < 64) cent[t] = sb[(t << 13) + far];
        __syncthreads();
        double dd = 0.0;
#pragma unroll
        for (int c = 0; c < 64; ++c) {
            double df = (double)p[c] - (double)cent[c];
            dd = fma(df, df, dd);
        }
        float d = (float)dd;
        distance = fminf(distance, d);
        unsigned long long key = ((unsigned long long)__float_as_uint(distance) << 32)
                               | (unsigned long long)(0xFFFFFFFFu - (unsigned)myn);
#pragma unroll
        for (int o = 16; o > 0; o >>= 1) {
            unsigned long long ok = __shfl_xor_sync(0xFFFFFFFFu, key, o);
            key = (ok > key) ? ok : key;
        }
        if ((t & 31) == 0) warp_best[t >> 5] = key;
        __syncthreads();
        if (t == 0) {
            unsigned long long kk = warp_best[0];
#pragma unroll
            for (int w = 1; w < 16; ++w) { unsigned long long o2 = warp_best[w]; kk = (o2 > kk) ? o2 : kk; }
            int slot = m & 7, par = m & 1;
            atomicMax(best + slot, kk);
            __threadfence();
            atomicAdd((unsigned int*)(g_count + b * 2 + par), 1u);
            unsigned target = 16u * (unsigned)(m / 2 + 1);
            while (cnt[par] < target) { }
            __threadfence();
            unsigned long long win = best[slot];
            int f = (int)(0xFFFFFFFFu - (unsigned)(win & 0xFFFFFFFFull));
            s_far = f;
            if (rank == 0) { g_idx[b * NCENT + m + 1] = f; best[(m + 4) & 7] = 0ull; }
        }
        __syncthreads();
        far = s_far;
    }
}

// ---------------- fp32 SGEMM (h1/q/wo; proven) -------------------------------
__global__ void __launch_bounds__(256, 2) sgemm_kernel(
    const float* __restrict__ A, const float* __restrict__ Bm, float* __restrict__ C,
    int Nd, int Kd, long long sB, long long sC,
    const float* __restrict__ bias, const float* __restrict__ addbuf, float scale)
{
    __shared__ float As[2][16][128];
    __shared__ float Bs[2][16][128];
    int batch = blockIdx.z;
    const float* Bb = Bm + (long long)batch * sB;
    float* Cb = C + (long long)batch * sC;
    int bm0 = blockIdx.y * 128, bn0 = blockIdx.x * 128;
    int t = threadIdx.x, row0 = (t >> 4) << 3, col0 = (t & 15) << 3;
    int ntiles = Kd >> 4;
    uint32_t sBs = (uint32_t)__cvta_generic_to_shared(&Bs[0][0][0]);
    float4 fa0, fa1;
    auto issueA = [&](int kt) {
        fa0 = *reinterpret_cast<const float4*>(A + (long long)(bm0 + (t >> 2)) * Kd + kt + ((t & 3) << 2));
        int v1 = t + 256;
        fa1 = *reinterpret_cast<const float4*>(A + (long long)(bm0 + (v1 >> 2)) * Kd + kt + ((v1 & 3) << 2));
    };
    auto storeA = [&](int bb) {
        int r0 = t >> 2, k0v = (t & 3) << 2;
        As[bb][k0v + 0][r0] = fa0.x; As[bb][k0v + 1][r0] = fa0.y;
        As[bb][k0v + 2][r0] = fa0.z; As[bb][k0v + 3][r0] = fa0.w;
        int v1 = t + 256, r1 = v1 >> 2, k1v = (v1 & 3) << 2;
        As[bb][k1v + 0][r1] = fa1.x; As[bb][k1v + 1][r1] = fa1.y;
        As[bb][k1v + 2][r1] = fa1.z; As[bb][k1v + 3][r1] = fa1.w;
    };
    auto issueB = [&](int bb, int kt) {
#pragma unroll
        for (int i2 = 0; i2 < 2; ++i2) {
            int v = t + i2 * 256, kk = v >> 5, nv = (v & 31) << 2;
            cp_async16(sBs + (uint32_t)((((bb << 11) | (kk << 7) | nv)) << 2),
                       Bb + (long long)(kt + kk) * Nd + bn0 + nv);
        }
    };
    float acc[8][8];
#pragma unroll
    for (int i = 0; i < 8; ++i)
#pragma unroll
        for (int j = 0; j < 8; ++j) acc[i][j] = 0.f;
    issueA(0); issueB(0, 0); storeA(0);
    cp_commit(); cp_wait_all();
    __syncthreads();
    int buf = 0;
    for (int it = 0; it < ntiles; ++it) {
        bool hn = (it + 1 < ntiles);
        if (hn) { issueA((it + 1) << 4); issueB(buf ^ 1, (it + 1) << 4); cp_commit(); }
        const float (*Asb)[128] = As[buf];
        const float (*Bsb)[128] = Bs[buf];
#pragma unroll
        for (int kk = 0; kk < 16; ++kk) {
            float ra[8], rb[8];
            *reinterpret_cast<float4*>(&ra[0]) = *reinterpret_cast<const float4*>(&Asb[kk][row0]);
            *reinterpret_cast<float4*>(&ra[4]) = *reinterpret_cast<const float4*>(&Asb[kk][row0 + 4]);
            *reinterpret_cast<float4*>(&rb[0]) = *reinterpret_cast<const float4*>(&Bsb[kk][col0]);
            *reinterpret_cast<float4*>(&rb[4]) = *reinterpret_cast<const float4*>(&Bsb[kk][col0 + 4]);
#pragma unroll
            for (int i = 0; i < 8; ++i)
#pragma unroll
                for (int j = 0; j < 8; ++j) acc[i][j] = fmaf(ra[i], rb[j], acc[i][j]);
        }
        if (hn) { storeA(buf ^ 1); cp_wait_all(); __syncthreads(); buf ^= 1; }
    }
#pragma unroll
    for (int i = 0; i < 8; ++i) {
        int r = bm0 + row0 + i;
        float bv = bias ? bias[r] : 0.f;
#pragma unroll
        for (int jv = 0; jv < 2; ++jv) {
            int cidx = bn0 + col0 + (jv << 2);
            float4 o;
            o.x = acc[i][jv * 4 + 0] * scale + bv; o.y = acc[i][jv * 4 + 1] * scale + bv;
            o.z = acc[i][jv * 4 + 2] * scale + bv; o.w = acc[i][jv * 4 + 3] * scale + bv;
            if (addbuf) {
                const float4 a4 = *reinterpret_cast<const float4*>(
                    addbuf + (long long)batch * sC + (long long)r * Nd + cidx);
                o.x += a4.x; o.y += a4.y; o.z += a4.z; o.w += a4.w;
            }
            *reinterpret_cast<float4*>(Cb + (long long)r * Nd + cidx) = o;
        }
    }
}

// ---------------- WMMA bf16-split GEMM, 2-stage pipelined --------------------
// C = scale*(A @ B^T). A[M,K], B[N,K] K-major bf16 (hi/lo). 128x128 CTA tile,
// 8 warps (4x2), warp computes 32x64. 3 terms: hh + hl + lh.
// Double-buffered K=16 stages: issue stage s+1 cp.async before computing s.
__global__ void __launch_bounds__(256) tc_gemm_kernel(
    const __nv_bfloat16* __restrict__ Ahg, const __nv_bfloat16* __restrict__ Alg,
    const __nv_bfloat16* __restrict__ Bhg, const __nv_bfloat16* __restrict__ Blg,
    float* __restrict__ C, int Nd, int Kd,
    long long sA, long long sB, long long sC,
    float scale, int ksplit)
{
    __shared__ __align__(128) __nv_bfloat16 sm[2][4][128][16];
    int t = threadIdx.x, wid = t >> 5;
    int bz = blockIdx.z, batch = bz / ksplit, ks = bz - batch * ksplit;
    int kchunk = Kd / ksplit, k0 = ks * kchunk, niter = kchunk >> 4;
    int bm0 = blockIdx.y << 7, bn0 = blockIdx.x << 7;
    const __nv_bfloat16* src4[4];
    src4[0] = Ahg + (long long)batch * sA + (long long)bm0 * Kd;
    src4[1] = Alg + (long long)batch * sA + (long long)bm0 * Kd;
    src4[2] = Bhg + (long long)batch * sB + (long long)bn0 * Kd;
    src4[3] = Blg + (long long)batch * sB + (long long)bn0 * Kd;
    int wm = wid & 3, wn = wid >> 2;

    wmma::fragment<wmma::accumulator, 16, 16, 16, float> acc[2][4];
#pragma unroll
    for (int i = 0; i < 2; ++i)
#pragma unroll
        for (int j = 0; j < 4; ++j) wmma::fill_fragment(acc[i][j], 0.f);

    uint32_t sbase = (uint32_t)__cvta_generic_to_shared(&sm[0][0][0][0]);
    int lrow = t >> 1, lhalf = t & 1;     // 2 threads per row, 16B each

    auto issue = [&](int stage, int kt) {
#pragma unroll
        for (int i = 0; i < 4; ++i) {
            cp_async16(sbase + (uint32_t)((stage << 14) + (i << 12) + (lrow << 5) + (lhalf << 4)),
                       src4[i] + (long long)lrow * Kd + kt + (lhalf << 3));
        }
        cp_commit();
    };

    issue(0, k0);
    int buf = 0;
    for (int it = 0; it < niter; ++it) {
        bool hn = (it + 1 < niter);
        if (hn) issue(buf ^ 1, k0 + ((it + 1) << 4));
        if (hn) cp_wait1(); else cp_wait_all();
        __syncthreads();

        wmma::fragment<wmma::matrix_a, 16, 16, 16, __nv_bfloat16, wmma::row_major> ah[2], al[2];
#pragma unroll
        for (int mf = 0; mf < 2; ++mf) {
            int r = wm * 32 + mf * 16;
            wmma::load_matrix_sync(ah[mf], &sm[buf][0][r][0], 16);
            wmma::load_matrix_sync(al[mf], &sm[buf][1][r][0], 16);
        }
#pragma unroll
        for (int nf = 0; nf < 4; ++nf) {
            int n = wn * 64 + nf * 16;
            wmma::fragment<wmma::matrix_b, 16, 16, 16, __nv_bfloat16, wmma::col_major> bh, bl;
            wmma::load_matrix_sync(bh, &sm[buf][2][n][0], 16);
            wmma::load_matrix_sync(bl, &sm[buf][3][n][0], 16);
#pragma unroll
            for (int mf = 0; mf < 2; ++mf) {
                wmma::mma_sync(acc[mf][nf], ah[mf], bh, acc[mf][nf]);
                wmma::mma_sync(acc[mf][nf], ah[mf], bl, acc[mf][nf]);
                wmma::mma_sync(acc[mf][nf], al[mf], bh, acc[mf][nf]);
            }
        }
        __syncthreads();
        buf ^= 1;
    }

    float* Cb = C + (long long)bz * sC;
#pragma unroll
    for (int mf = 0; mf < 2; ++mf)
#pragma unroll
        for (int nf = 0; nf < 4; ++nf) {
#pragma unroll
            for (int e = 0; e < acc[mf][nf].num_elements; ++e) acc[mf][nf].x[e] *= scale;
            wmma::store_matrix_sync(
                Cb + (long long)(bm0 + wm * 32 + mf * 16) * Nd + bn0 + wn * 64 + nf * 16,
                acc[mf][nf], Nd, wmma::mem_row_major);
        }
}

// ---------------- converters --------------------------------------------------
__global__ void __launch_bounds__(256) split_kernel(
    const float* __restrict__ src, __nv_bfloat16* __restrict__ hi,
    __nv_bfloat16* __restrict__ lo, int total4)
{
    for (int v = blockIdx.x * blockDim.x + threadIdx.x; v < total4; v += gridDim.x * blockDim.x) {
        float4 f = reinterpret_cast<const float4*>(src)[v];
        __nv_bfloat16 h0 = __float2bfloat16(f.x), h1 = __float2bfloat16(f.y);
        __nv_bfloat16 h2 = __float2bfloat16(f.z), h3 = __float2bfloat16(f.w);
        __nv_bfloat162 a, b;
        a.x = h0; a.y = h1; b.x = h2; b.y = h3;
        reinterpret_cast<__nv_bfloat162*>(hi)[v * 2] = a;
        reinterpret_cast<__nv_bfloat162*>(hi)[v * 2 + 1] = b;
        a.x = __float2bfloat16(f.x - __bfloat162float(h0));
        a.y = __float2bfloat16(f.y - __bfloat162float(h1));
        b.x = __float2bfloat16(f.z - __bfloat162float(h2));
        b.y = __float2bfloat16(f.w - __bfloat162float(h3));
        reinterpret_cast<__nv_bfloat162*>(lo)[v * 2] = a;
        reinterpret_cast<__nv_bfloat162*>(lo)[v * 2 + 1] = b;
    }
}

// src [b][C][N] -> dst [b][N][C] bf16 split. grid(N/32, C/32, BATCH), 256 thr.
__global__ void __launch_bounds__(256) tsplit_kernel(
    const float* __restrict__ src, __nv_bfloat16* __restrict__ hi,
    __nv_bfloat16* __restrict__ lo, int C, int N)
{
    __shared__ float tile[32][33];
    int b = blockIdx.z, c0 = blockIdx.y * 32, n0 = blockIdx.x * 32;
    int tx = threadIdx.x & 31, ty = threadIdx.x >> 5;
    const float* s = src + (long long)b * C * N;
#pragma unroll
    for (int i = 0; i < 32; i += 8)
        tile[ty + i][tx] = s[(long long)(c0 + ty + i) * N + n0 + tx];
    __syncthreads();
    __nv_bfloat16* H = hi + ((long long)b * N + n0) * C + c0;
    __nv_bfloat16* L = lo + ((long long)b * N + n0) * C + c0;
#pragma unroll
    for (int i = 0; i < 32; i += 8) {
        float x = tile[tx][ty + i];
        __nv_bfloat16 h = __float2bfloat16(x);
        H[(long long)(ty + i) * C + tx] = h;
        L[(long long)(ty + i) * C + tx] = __float2bfloat16(x - __bfloat162float(h));
    }
}

// ---------------- BN / addbias / gather / softmax / reduce -------------------
__global__ void __launch_bounds__(256) bn_stats_kernel(
    const float* __restrict__ x, const float* __restrict__ gamma,
    const float* __restrict__ beta, float* __restrict__ scale,
    float* __restrict__ shift, int Cd)
{
    __shared__ float rs[8], rq[8];
    int c = blockIdx.x, t = threadIdx.x;
    float s = 0.f, q = 0.f;
    for (int b = 0; b < BATCH; ++b) {
        const float4* p = reinterpret_cast<const float4*>(x + ((long long)b * Cd + c) * NPTS);
        for (int v = t; v < NPTS / 4; v += 256) {
            float4 f = p[v];
            s += f.x + f.y + f.z + f.w;
            q += f.x * f.x + f.y * f.y + f.z * f.z + f.w * f.w;
        }
    }
#pragma unroll
    for (int o = 16; o; o >>= 1) {
        s += __shfl_xor_sync(0xFFFFFFFFu, s, o);
        q += __shfl_xor_sync(0xFFFFFFFFu, q, o);
    }
    if ((t & 31) == 0) { rs[t >> 5] = s; rq[t >> 5] = q; }
    __syncthreads();
    if (t == 0) {
        float S = 0.f, Q = 0.f;
#pragma unroll
        for (int w = 0; w < 8; ++w) { S += rs[w]; Q += rq[w]; }
        const float inv = 1.f / (float)(BATCH * NPTS);
        float mean = S * inv, var = Q * inv - mean * mean;
        float rstd = rsqrtf(var + 1e-5f), g = gamma[c];
        scale[c] = rstd * g;
        shift[c] = beta[c] - mean * rstd * g;
    }
}

__global__ void __launch_bounds__(256) bn_apply_kernel(
    float* __restrict__ x, const float* __restrict__ scale,
    const float* __restrict__ shift, int Cd)
{
    int total = BATCH * Cd * (NPTS / 4);
    for (int v = blockIdx.x * blockDim.x + threadIdx.x; v < total; v += gridDim.x * blockDim.x) {
        int c = (v >> 11) % Cd;
        float s = scale[c], sh = shift[c];
        float4 f = reinterpret_cast<float4*>(x)[v];
        f.x = f.x * s + sh; f.y = f.y * s + sh; f.z = f.z * s + sh; f.w = f.w * s + sh;
        f.x = f.x > 0.f ? f.x : 0.2f * f.x; f.y = f.y > 0.f ? f.y : 0.2f * f.y;
        f.z = f.z > 0.f ? f.z : 0.2f * f.z; f.w = f.w > 0.f ? f.w : 0.2f * f.w;
        reinterpret_cast<float4*>(x)[v] = f;
    }
}

__global__ void __launch_bounds__(256) addbias_kernel(
    float* __restrict__ x, const float* __restrict__ bias, int Cd)
{
    int total = BATCH * Cd * (NPTS / 4);
    for (int v = blockIdx.x * blockDim.x + threadIdx.x; v < total; v += gridDim.x * blockDim.x) {
        int c = (v >> 11) % Cd;
        float bv = bias[c];
        float4 f = reinterpret_cast<float4*>(x)[v];
        f.x += bv; f.y += bv; f.z += bv; f.w += bv;
        reinterpret_cast<float4*>(x)[v] = f;
    }
}

__global__ void __launch_bounds__(256) gather_kernel(
    const float* __restrict__ xyz, float* __restrict__ out_xyz)
{
    int v = blockIdx.x * blockDim.x + threadIdx.x;
    if (v < BATCH * 256 * NCENT) {
        int b = v >> 17, rem = v & 131071, c = rem >> 9, m = rem & 511;
        int id = g_idx[b * NCENT + m];
        g_cent[v] = g_feat[((long long)b * 256 + c) * NPTS + id];
    }
    if (v < BATCH * 3 * NCENT) {
        int b = v / (3 * NCENT), rem = v - b * 3 * NCENT, c = rem >> 9, m = rem & 511;
        int id = g_idx[b * NCENT + m];
        out_xyz[v] = xyz[((long long)b * 3 + c) * NPTS + id];
    }
}

__global__ void __launch_bounds__(256) softmax_kernel()
{
    __shared__ float red[8];
    long long row = blockIdx.x;
    float4* p = reinterpret_cast<float4*>(g_logits + row * NPTS);
    int t = threadIdx.x;
    float4 v[8];
#pragma unroll
    for (int i = 0; i < 8; ++i) v[i] = p[t + (i << 8)];
    float mx = -1e30f;
#pragma unroll
    for (int i = 0; i < 8; ++i)
        mx = fmaxf(mx, fmaxf(fmaxf(v[i].x, v[i].y), fmaxf(v[i].z, v[i].w)));
#pragma unroll
    for (int o = 16; o; o >>= 1) mx = fmaxf(mx, __shfl_xor_sync(0xFFFFFFFFu, mx, o));
    if ((t & 31) == 0) red[t >> 5] = mx;
    __syncthreads();
#pragma unroll
    for (int w = 0; w < 8; ++w) mx = fmaxf(mx, red[w]);
    __syncthreads();
    float s = 0.f;
#pragma unroll
    for (int i = 0; i < 8; ++i) {
        v[i].x = __expf(v[i].x - mx); v[i].y = __expf(v[i].y - mx);
        v[i].z = __expf(v[i].z - mx); v[i].w = __expf(v[i].w - mx);
        s += v[i].x + v[i].y + v[i].z + v[i].w;
    }
#pragma unroll
    for (int o = 16; o; o >>= 1) s += __shfl_xor_sync(0xFFFFFFFFu, s, o);
    if ((t & 31) == 0) red[t >> 5] = s;
    __syncthreads();
    s = 0.f;
#pragma unroll
    for (int w = 0; w < 8; ++w) s += red[w];
    float inv = 1.f / s;
#pragma unroll
    for (int i = 0; i < 8; ++i) {
        v[i].x *= inv; v[i].y *= inv; v[i].z *= inv; v[i].w *= inv;
        p[t + (i << 8)] = v[i];
    }
}

__global__ void __launch_bounds__(256) reduceK_kernel()
{
    int v = blockIdx.x * blockDim.x + threadIdx.x;
    int total = BATCH * 256 * NCENT / 4;
    if (v >= total) return;
    int b = v >> 15, i = v & 32767;
    const float4* pp = reinterpret_cast<const float4*>(g_attpart);
    float4 s = pp[((long long)b * KSPLIT_PV + 0) * 32768 + i];
#pragma unroll
    for (int ks = 1; ks < KSPLIT_PV; ++ks) {
        float4 x = pp[((long long)b * KSPLIT_PV + ks) * 32768 + i];
        s.x += x.x; s.y += x.y; s.z += x.z; s.w += x.w;
    }
    reinterpret_cast<float4*>(g_att)[v] = s;
}

// ---------------- host launcher ---------------------------------------------
static float* sym(const void* s) { void* p = nullptr; cudaGetSymbolAddress(&p, (const void*)s); return (float*)p; }
static __nv_bfloat16* symb(const void* s) { void* p = nullptr; cudaGetSymbolAddress(&p, (const void*)s); return (__nv_bfloat16*)p; }

extern "C" void kernel_launch(void* const* d_in, const int* in_sizes, int n_in,
                              void* d_out, int out_size)
{
    const float* xyz = (const float*)d_in[0];
    const float* pf  = (const float*)d_in[1];
    const float* w1  = (const float*)d_in[2];
    const float* b1  = (const float*)d_in[3];
    const float* g1  = (const float*)d_in[4];
    const float* be1 = (const float*)d_in[5];
    const float* w2  = (const float*)d_in[6];
    const float* g2  = (const float*)d_in[8];
    const float* be2 = (const float*)d_in[9];
    const float* w3  = (const float*)d_in[10];
    const float* b3  = (const float*)d_in[11];
    const float* wq  = (const float*)d_in[12];
    const float* wk  = (const float*)d_in[13];
    const float* wv  = (const float*)d_in[14];
    const float* wo  = (const float*)d_in[15];
    const int*   far0 = (const int*)d_in[16];
    float* out = (float*)d_out;

    float* p_sup = sym(g_support); float* p_h1 = sym(g_h1); float* p_h2 = sym(g_h2);
    float* p_feat = sym(g_feat); float* p_k = sym(g_kbuf); float* p_v = sym(g_vbuf);
    float* p_q = sym(g_qbuf); float* p_cent = sym(g_cent); float* p_log = sym(g_logits);
    float* p_ap = sym(g_attpart); float* p_att = sym(g_att);
    float* p_s1 = sym(g_bns1); float* p_sh1 = sym(g_bnh1);
    float* p_s2 = sym(g_bns2); float* p_sh2 = sym(g_bnh2);

    __nv_bfloat16 *w2h = symb(g_w2h), *w2l = symb(g_w2l), *w3h = symb(g_w3h), *w3l = symb(g_w3l);
    __nv_bfloat16 *wkh = symb(g_wkh), *wkl = symb(g_wkl), *wvh = symb(g_wvh), *wvl = symb(g_wvl);
    __nv_bfloat16 *h1Th = symb(g_h1Th), *h1Tl = symb(g_h1Tl), *h2Th = symb(g_h2Th), *h2Tl = symb(g_h2Tl);
    __nv_bfloat16 *fTh = symb(g_fTh), *fTl = symb(g_fTl), *kTh = symb(g_kTh), *kTl = symb(g_kTl);
    __nv_bfloat16 *vh = symb(g_vh), *vl = symb(g_vl), *qTh = symb(g_qTh), *qTl = symb(g_qTl);
    __nv_bfloat16 *ph = symb(g_ph), *pl = symb(g_pl);

    fps_init_kernel<<<1, 64>>>();
    support_kernel<<<1024, 256>>>(xyz, pf);
    fps_kernel<<<128, 512>>>(far0);

    // weight splits
    split_kernel<<<32, 256>>>(w2, w2h, w2l, 256 * 128 / 4);
    split_kernel<<<64, 256>>>(w3, w3h, w3l, 256 * 256 / 4);
    split_kernel<<<64, 256>>>(wk, wkh, wkl, 256 * 256 / 4);
    split_kernel<<<64, 256>>>(wv, wvh, wvl, 256 * 256 / 4);

    // h1 = w1 @ support + b1 (fp32), BN1, transpose-split
    sgemm_kernel<<<dim3(64, 1, 8), 256>>>(w1, p_sup, p_h1, NPTS, 64,
        64LL * NPTS, 128LL * NPTS, b1, nullptr, 1.f);
    bn_stats_kernel<<<128, 256>>>(p_h1, g1, be1, p_s1, p_sh1, 128);
    bn_apply_kernel<<<2048, 256>>>(p_h1, p_s1, p_sh1, 128);
    tsplit_kernel<<<dim3(256, 4, 8), 256>>>(p_h1, h1Th, h1Tl, 128, NPTS);

    // h2 = w2 @ h1' (tc; b2 cancels inside BN), BN2, transpose-split
    tc_gemm_kernel<<<dim3(64, 2, 8), 256>>>(w2h, w2l, h1Th, h1Tl, p_h2,
        NPTS, 128, 0LL, (long long)NPTS * 128, 256LL * NPTS, 1.f, 1);
    bn_stats_kernel<<<256, 256>>>(p_h2, g2, be2, p_s2, p_sh2, 256);
    bn_apply_kernel<<<4096, 256>>>(p_h2, p_s2, p_sh2, 256);
    tsplit_kernel<<<dim3(256, 8, 8), 256>>>(p_h2, h2Th, h2Tl, 256, NPTS);

    // feat = w3 @ h2' (tc) + b3
    tc_gemm_kernel<<<dim3(64, 2, 8), 256>>>(w3h, w3l, h2Th, h2Tl, p_feat,
        NPTS, 256, 0LL, (long long)NPTS * 256, 256LL * NPTS, 1.f, 1);
    addbias_kernel<<<4096, 256>>>(p_feat, b3, 256);
    gather_kernel<<<4096, 256>>>(xyz, out);
    tsplit_kernel<<<dim3(256, 8, 8), 256>>>(p_feat, fTh, fTl, 256, NPTS);

    // k, v (tc)
    tc_gemm_kernel<<<dim3(64, 2, 8), 256>>>(wkh, wkl, fTh, fTl, p_k,
        NPTS, 256, 0LL, (long long)NPTS * 256, 256LL * NPTS, 1.f, 1);
    tc_gemm_kernel<<<dim3(64, 2, 8), 256>>>(wvh, wvl, fTh, fTl, p_v,
        NPTS, 256, 0LL, (long long)NPTS * 256, 256LL * NPTS, 1.f, 1);
    tsplit_kernel<<<dim3(256, 8, 8), 256>>>(p_k, kTh, kTl, 256, NPTS);
    split_kernel<<<4096, 256>>>(p_v, vh, vl, BATCH * 256 * NPTS / 4);

    // q = wq @ centroids (fp32) then transpose-split
    sgemm_kernel<<<dim3(4, 2, 8), 256>>>(wq, p_cent, p_q, NCENT, 256,
        256LL * NCENT, 256LL * NCENT, nullptr, nullptr, 1.f);
    tsplit_kernel<<<dim3(16, 8, 8), 256>>>(p_q, qTh, qTl, 256, NCENT);

    // logits = (q^T k) / 16 (tc)
    tc_gemm_kernel<<<dim3(64, 4, 8), 256>>>(qTh, qTl, kTh, kTl, p_log,
        NPTS, 256, (long long)NCENT * 256, (long long)NPTS * 256,
        (long long)NCENT * NPTS, 0.0625f, 1);

    softmax_kernel<<<BATCH * NCENT, 256>>>();
    split_kernel<<<4096, 256>>>(p_log, ph, pl, BATCH * NCENT * NPTS / 4);

    // att = probs @ v^T (tc, split-K 8)
    tc_gemm_kernel<<<dim3(4, 2, 8 * KSPLIT_PV), 256>>>(vh, vl, ph, pl, p_ap,
        NCENT, NPTS, 256LL * NPTS, (long long)NCENT * NPTS, 256LL * NCENT,
        1.f, KSPLIT_PV);
    reduceK_kernel<<<1024, 256>>>();

    // out2 = centroids + wo @ att (fp32)
    sgemm_kernel<<<dim3(4, 2, 8), 256>>>(wo, p_att, out + BATCH * 3 * NCENT, NCENT, 256,
        256LL * NCENT, 256LL * NCENT, nullptr, p_cent, 1.f);
}

// round 15
// speedup vs baseline: 1.2376x; 1.0396x over previous
#include <cuda_runtime.h>
#include <cuda_bf16.h>
#include <mma.h>
#include <cstdint>

using namespace nvcuda;

#define BATCH 8
#define NPTS  8192
#define NCENT 512
#define KSPLIT_PV 8

// ---------------- fp32 scratch ----------------------------------------------
__device__ float g_support[BATCH * 64 * NPTS];
__device__ float g_h1[BATCH * 128 * NPTS];
__device__ float g_h2[BATCH * 256 * NPTS];
__device__ float g_feat[BATCH * 256 * NPTS];
__device__ float g_kbuf[BATCH * 256 * NPTS];
__device__ float g_vbuf[BATCH * 256 * NPTS];
__device__ float g_qbuf[BATCH * 256 * NCENT];
__device__ float g_cent[BATCH * 256 * NCENT];
__device__ float g_logits[BATCH * NCENT * NPTS];
__device__ float g_attpart[BATCH * KSPLIT_PV * 256 * NCENT];
__device__ float g_att[BATCH * 256 * NCENT];
__device__ int   g_idx[BATCH * NCENT];
__device__ float g_bns1[128], g_bnh1[128];
__device__ float g_bns2[256], g_bnh2[256];
__device__ unsigned long long g_best[BATCH * 8];
__device__ unsigned int       g_count[BATCH * 2];

// ---------------- bf16 split buffers (hi/lo) --------------------------------
__device__ __nv_bfloat16 g_w2h[256*128],  g_w2l[256*128];
__device__ __nv_bfloat16 g_w3h[256*256],  g_w3l[256*256];
__device__ __nv_bfloat16 g_wkh[256*256],  g_wkl[256*256];
__device__ __nv_bfloat16 g_wvh[256*256],  g_wvl[256*256];
__device__ __nv_bfloat16 g_h1Th[BATCH*NPTS*128], g_h1Tl[BATCH*NPTS*128];
__device__ __nv_bfloat16 g_h2Th[BATCH*NPTS*256], g_h2Tl[BATCH*NPTS*256];
__device__ __nv_bfloat16 g_fTh[BATCH*NPTS*256],  g_fTl[BATCH*NPTS*256];
__device__ __nv_bfloat16 g_kTh[BATCH*NPTS*256],  g_kTl[BATCH*NPTS*256];
__device__ __nv_bfloat16 g_vh[BATCH*256*NPTS],   g_vl[BATCH*256*NPTS];
__device__ __nv_bfloat16 g_qTh[BATCH*NCENT*256], g_qTl[BATCH*NCENT*256];
__device__ __nv_bfloat16 g_ph[BATCH*NCENT*NPTS], g_pl[BATCH*NCENT*NPTS];

// ---------------- helpers ----------------------------------------------------
__device__ __forceinline__ void cp_async16(uint32_t dst, const void* src) {
    asm volatile("cp.async.cg.shared.global [%0], [%1], 16;\n" :: "r"(dst), "l"(src));
}
__device__ __forceinline__ void cp_commit() { asm volatile("cp.async.commit_group;\n"); }
__device__ __forceinline__ void cp_wait_all() { asm volatile("cp.async.wait_group 0;\n" ::: "memory"); }
__device__ __forceinline__ void cp_wait1() { asm volatile("cp.async.wait_group 1;\n" ::: "memory"); }
__device__ __forceinline__ void cp_wait2() { asm volatile("cp.async.wait_group 2;\n" ::: "memory"); }

// ---------------- init / support / FPS (proven) ------------------------------
__global__ void fps_init_kernel()
{
    int t = threadIdx.x;
    if (t < BATCH * 8) g_best[t] = 0ull;
    if (t < BATCH * 2) g_count[t] = 0u;
}

__global__ void __launch_bounds__(256) support_kernel(
    const float* __restrict__ xyz, const float* __restrict__ pf)
{
    int total = BATCH * 64 * (NPTS / 4);
    for (int v = blockIdx.x * blockDim.x + threadIdx.x; v < total; v += gridDim.x * blockDim.x) {
        int b = v >> 17, rem = v & 131071, c = rem >> 11, nv = rem & 2047;
        float4 f;
        if (c < 3) f = reinterpret_cast<const float4*>(xyz + ((long long)b * 3 + c) * NPTS)[nv];
        else       f = reinterpret_cast<const float4*>(pf + ((long long)b * 61 + (c - 3)) * NPTS)[nv];
        reinterpret_cast<float4*>(g_support)[v] = f;
    }
}

__global__ void __launch_bounds__(512, 1) fps_kernel(const int* __restrict__ far0)
{
    __shared__ float cent[64];
    __shared__ unsigned long long warp_best[16];
    __shared__ int s_far;
    int rank = blockIdx.x & 15, b = blockIdx.x >> 4, t = threadIdx.x;
    const float* sb = g_support + (long long)b * 64 * NPTS;
    int myn = (rank << 9) + t;
    float p[64];
#pragma unroll
    for (int c = 0; c < 64; ++c) p[c] = sb[(c << 13) + myn];
    float distance = 1e10f;
    int far = far0[b];
    if (rank == 0 && t == 0) g_idx[b * NCENT] = far;
    unsigned long long* best = g_best + b * 8;
    volatile unsigned int* cnt = (volatile unsigned int*)(g_count + b * 2);
    for (int m = 0; m < NCENT - 1; ++m) {
        if (t < 64) cent[t] = sb[(t << 13) + far];
        __syncthreads();
        double dd = 0.0;
#pragma unroll
        for (int c = 0; c < 64; ++c) {
            double df = (double)p[c] - (double)cent[c];
            dd = fma(df, df, dd);
        }
        float d = (float)dd;
        distance = fminf(distance, d);
        unsigned long long key = ((unsigned long long)__float_as_uint(distance) << 32)
                               | (unsigned long long)(0xFFFFFFFFu - (unsigned)myn);
#pragma unroll
        for (int o = 16; o > 0; o >>= 1) {
            unsigned long long ok = __shfl_xor_sync(0xFFFFFFFFu, key, o);
            key = (ok > key) ? ok : key;
        }
        if ((t & 31) == 0) warp_best[t >> 5] = key;
        __syncthreads();
        if (t == 0) {
            unsigned long long kk = warp_best[0];
#pragma unroll
            for (int w = 1; w < 16; ++w) { unsigned long long o2 = warp_best[w]; kk = (o2 > kk) ? o2 : kk; }
            int slot = m & 7, par = m & 1;
            atomicMax(best + slot, kk);
            __threadfence();
            atomicAdd((unsigned int*)(g_count + b * 2 + par), 1u);
            unsigned target = 16u * (unsigned)(m / 2 + 1);
            while (cnt[par] < target) { }
            __threadfence();
            unsigned long long win = best[slot];
            int f = (int)(0xFFFFFFFFu - (unsigned)(win & 0xFFFFFFFFull));
            s_far = f;
            if (rank == 0) { g_idx[b * NCENT + m + 1] = f; best[(m + 4) & 7] = 0ull; }
        }
        __syncthreads();
        far = s_far;
    }
}

// ---------------- fp32 SGEMM (h1/q/wo; proven) -------------------------------
__global__ void __launch_bounds__(256, 2) sgemm_kernel(
    const float* __restrict__ A, const float* __restrict__ Bm, float* __restrict__ C,
    int Nd, int Kd, long long sB, long long sC,
    const float* __restrict__ bias, const float* __restrict__ addbuf, float scale)
{
    __shared__ float As[2][16][128];
    __shared__ float Bs[2][16][128];
    int batch = blockIdx.z;
    const float* Bb = Bm + (long long)batch * sB;
    float* Cb = C + (long long)batch * sC;
    int bm0 = blockIdx.y * 128, bn0 = blockIdx.x * 128;
    int t = threadIdx.x, row0 = (t >> 4) << 3, col0 = (t & 15) << 3;
    int ntiles = Kd >> 4;
    uint32_t sBs = (uint32_t)__cvta_generic_to_shared(&Bs[0][0][0]);
    float4 fa0, fa1;
    auto issueA = [&](int kt) {
        fa0 = *reinterpret_cast<const float4*>(A + (long long)(bm0 + (t >> 2)) * Kd + kt + ((t & 3) << 2));
        int v1 = t + 256;
        fa1 = *reinterpret_cast<const float4*>(A + (long long)(bm0 + (v1 >> 2)) * Kd + kt + ((v1 & 3) << 2));
    };
    auto storeA = [&](int bb) {
        int r0 = t >> 2, k0v = (t & 3) << 2;
        As[bb][k0v + 0][r0] = fa0.x; As[bb][k0v + 1][r0] = fa0.y;
        As[bb][k0v + 2][r0] = fa0.z; As[bb][k0v + 3][r0] = fa0.w;
        int v1 = t + 256, r1 = v1 >> 2, k1v = (v1 & 3) << 2;
        As[bb][k1v + 0][r1] = fa1.x; As[bb][k1v + 1][r1] = fa1.y;
        As[bb][k1v + 2][r1] = fa1.z; As[bb][k1v + 3][r1] = fa1.w;
    };
    auto issueB = [&](int bb, int kt) {
#pragma unroll
        for (int i2 = 0; i2 < 2; ++i2) {
            int v = t + i2 * 256, kk = v >> 5, nv = (v & 31) << 2;
            cp_async16(sBs + (uint32_t)((((bb << 11) | (kk << 7) | nv)) << 2),
                       Bb + (long long)(kt + kk) * Nd + bn0 + nv);
        }
    };
    float acc[8][8];
#pragma unroll
    for (int i = 0; i < 8; ++i)
#pragma unroll
        for (int j = 0; j < 8; ++j) acc[i][j] = 0.f;
    issueA(0); issueB(0, 0); storeA(0);
    cp_commit(); cp_wait_all();
    __syncthreads();
    int buf = 0;
    for (int it = 0; it < ntiles; ++it) {
        bool hn = (it + 1 < ntiles);
        if (hn) { issueA((it + 1) << 4); issueB(buf ^ 1, (it + 1) << 4); cp_commit(); }
        const float (*Asb)[128] = As[buf];
        const float (*Bsb)[128] = Bs[buf];
#pragma unroll
        for (int kk = 0; kk < 16; ++kk) {
            float ra[8], rb[8];
            *reinterpret_cast<float4*>(&ra[0]) = *reinterpret_cast<const float4*>(&Asb[kk][row0]);
            *reinterpret_cast<float4*>(&ra[4]) = *reinterpret_cast<const float4*>(&Asb[kk][row0 + 4]);
            *reinterpret_cast<float4*>(&rb[0]) = *reinterpret_cast<const float4*>(&Bsb[kk][col0]);
            *reinterpret_cast<float4*>(&rb[4]) = *reinterpret_cast<const float4*>(&Bsb[kk][col0 + 4]);
#pragma unroll
            for (int i = 0; i < 8; ++i)
#pragma unroll
                for (int j = 0; j < 8; ++j) acc[i][j] = fmaf(ra[i], rb[j], acc[i][j]);
        }
        if (hn) { storeA(buf ^ 1); cp_wait_all(); __syncthreads(); buf ^= 1; }
    }
#pragma unroll
    for (int i = 0; i < 8; ++i) {
        int r = bm0 + row0 + i;
        float bv = bias ? bias[r] : 0.f;
#pragma unroll
        for (int jv = 0; jv < 2; ++jv) {
            int cidx = bn0 + col0 + (jv << 2);
            float4 o;
            o.x = acc[i][jv * 4 + 0] * scale + bv; o.y = acc[i][jv * 4 + 1] * scale + bv;
            o.z = acc[i][jv * 4 + 2] * scale + bv; o.w = acc[i][jv * 4 + 3] * scale + bv;
            if (addbuf) {
                const float4 a4 = *reinterpret_cast<const float4*>(
                    addbuf + (long long)batch * sC + (long long)r * Nd + cidx);
                o.x += a4.x; o.y += a4.y; o.z += a4.z; o.w += a4.w;
            }
            *reinterpret_cast<float4*>(Cb + (long long)r * Nd + cidx) = o;
        }
    }
}

// ---------------- WMMA bf16-split GEMM, 3-stage pipelined --------------------
// C = scale*(A @ B^T). 128x128 CTA tile, 8 warps (4x2), warp 32x64.
// 3 terms: hh + hl + lh. Two K=16 stages in flight (wait_group 2).
__global__ void __launch_bounds__(256) tc_gemm_kernel(
    const __nv_bfloat16* __restrict__ Ahg, const __nv_bfloat16* __restrict__ Alg,
    const __nv_bfloat16* __restrict__ Bhg, const __nv_bfloat16* __restrict__ Blg,
    float* __restrict__ C, int Nd, int Kd,
    long long sA, long long sB, long long sC,
    float scale, int ksplit)
{
    __shared__ __align__(128) __nv_bfloat16 sm[3][4][128][16];
    int t = threadIdx.x, wid = t >> 5;
    int bz = blockIdx.z, batch = bz / ksplit, ks = bz - batch * ksplit;
    int kchunk = Kd / ksplit, k0 = ks * kchunk, niter = kchunk >> 4;
    int bm0 = blockIdx.y << 7, bn0 = blockIdx.x << 7;
    const __nv_bfloat16* src4[4];
    src4[0] = Ahg + (long long)batch * sA + (long long)bm0 * Kd;
    src4[1] = Alg + (long long)batch * sA + (long long)bm0 * Kd;
    src4[2] = Bhg + (long long)batch * sB + (long long)bn0 * Kd;
    src4[3] = Blg + (long long)batch * sB + (long long)bn0 * Kd;
    int wm = wid & 3, wn = wid >> 2;

    wmma::fragment<wmma::accumulator, 16, 16, 16, float> acc[2][4];
#pragma unroll
    for (int i = 0; i < 2; ++i)
#pragma unroll
        for (int j = 0; j < 4; ++j) wmma::fill_fragment(acc[i][j], 0.f);

    uint32_t sbase = (uint32_t)__cvta_generic_to_shared(&sm[0][0][0][0]);
    int lrow = t >> 1, lhalf = t & 1;

    auto issue = [&](int stage, int kt) {
#pragma unroll
        for (int i = 0; i < 4; ++i) {
            cp_async16(sbase + (uint32_t)(stage * 16384 + (i << 12) + (lrow << 5) + (lhalf << 4)),
                       src4[i] + (long long)lrow * Kd + kt + (lhalf << 3));
        }
        cp_commit();
    };

    issue(0, k0);
    if (niter > 1) issue(1, k0 + 16);
    for (int it = 0; it < niter; ++it) {
        int buf = it % 3;
        if (it + 2 < niter) { issue((it + 2) % 3, k0 + ((it + 2) << 4)); cp_wait2(); }
        else if (it + 1 < niter) cp_wait1();
        else cp_wait_all();
        __syncthreads();

        wmma::fragment<wmma::matrix_a, 16, 16, 16, __nv_bfloat16, wmma::row_major> ah[2], al[2];
#pragma unroll
        for (int mf = 0; mf < 2; ++mf) {
            int r = wm * 32 + mf * 16;
            wmma::load_matrix_sync(ah[mf], &sm[buf][0][r][0], 16);
            wmma::load_matrix_sync(al[mf], &sm[buf][1][r][0], 16);
        }
#pragma unroll
        for (int nf = 0; nf < 4; ++nf) {
            int n = wn * 64 + nf * 16;
            wmma::fragment<wmma::matrix_b, 16, 16, 16, __nv_bfloat16, wmma::col_major> bh, bl;
            wmma::load_matrix_sync(bh, &sm[buf][2][n][0], 16);
            wmma::load_matrix_sync(bl, &sm[buf][3][n][0], 16);
#pragma unroll
            for (int mf = 0; mf < 2; ++mf) {
                wmma::mma_sync(acc[mf][nf], ah[mf], bh, acc[mf][nf]);
                wmma::mma_sync(acc[mf][nf], ah[mf], bl, acc[mf][nf]);
                wmma::mma_sync(acc[mf][nf], al[mf], bh, acc[mf][nf]);
            }
        }
        __syncthreads();
    }

    float* Cb = C + (long long)bz * sC;
#pragma unroll
    for (int mf = 0; mf < 2; ++mf)
#pragma unroll
        for (int nf = 0; nf < 4; ++nf) {
#pragma unroll
            for (int e = 0; e < acc[mf][nf].num_elements; ++e) acc[mf][nf].x[e] *= scale;
            wmma::store_matrix_sync(
                Cb + (long long)(bm0 + wm * 32 + mf * 16) * Nd + bn0 + wn * 64 + nf * 16,
                acc[mf][nf], Nd, wmma::mem_row_major);
        }
}

// ---------------- converters --------------------------------------------------
__global__ void __launch_bounds__(256) split_kernel(
    const float* __restrict__ src, __nv_bfloat16* __restrict__ hi,
    __nv_bfloat16* __restrict__ lo, int total4)
{
    for (int v = blockIdx.x * blockDim.x + threadIdx.x; v < total4; v += gridDim.x * blockDim.x) {
        float4 f = reinterpret_cast<const float4*>(src)[v];
        __nv_bfloat16 h0 = __float2bfloat16(f.x), h1 = __float2bfloat16(f.y);
        __nv_bfloat16 h2 = __float2bfloat16(f.z), h3 = __float2bfloat16(f.w);
        __nv_bfloat162 a, b;
        a.x = h0; a.y = h1; b.x = h2; b.y = h3;
        reinterpret_cast<__nv_bfloat162*>(hi)[v * 2] = a;
        reinterpret_cast<__nv_bfloat162*>(hi)[v * 2 + 1] = b;
        a.x = __float2bfloat16(f.x - __bfloat162float(h0));
        a.y = __float2bfloat16(f.y - __bfloat162float(h1));
        b.x = __float2bfloat16(f.z - __bfloat162float(h2));
        b.y = __float2bfloat16(f.w - __bfloat162float(h3));
        reinterpret_cast<__nv_bfloat162*>(lo)[v * 2] = a;
        reinterpret_cast<__nv_bfloat162*>(lo)[v * 2 + 1] = b;
    }
}

// src [b][C][N] -> dst [b][N][C] bf16 split, with optional fused pre-op.
// MODE 0: plain. MODE 1: BN affine + LeakyReLU (p1=scale, p2=shift).
// MODE 2: add bias (p1=bias).
template<int MODE>
__global__ void __launch_bounds__(256) tsplit_kernel(
    const float* __restrict__ src, __nv_bfloat16* __restrict__ hi,
    __nv_bfloat16* __restrict__ lo, const float* __restrict__ p1,
    const float* __restrict__ p2, int C, int N)
{
    __shared__ float tile[32][33];
    int b = blockIdx.z, c0 = blockIdx.y * 32, n0 = blockIdx.x * 32;
    int tx = threadIdx.x & 31, ty = threadIdx.x >> 5;
    const float* s = src + (long long)b * C * N;
#pragma unroll
    for (int i = 0; i < 32; i += 8)
        tile[ty + i][tx] = s[(long long)(c0 + ty + i) * N + n0 + tx];
    __syncthreads();
    __nv_bfloat16* H = hi + ((long long)b * N + n0) * C + c0;
    __nv_bfloat16* L = lo + ((long long)b * N + n0) * C + c0;
    float sc = 0.f, sh = 0.f;
    if (MODE == 1) { sc = p1[c0 + tx]; sh = p2[c0 + tx]; }
    if (MODE == 2) { sc = p1[c0 + tx]; }
#pragma unroll
    for (int i = 0; i < 32; i += 8) {
        float x = tile[tx][ty + i];
        if (MODE == 1) {
            x = x * sc + sh;
            x = x > 0.f ? x : 0.2f * x;
        }
        if (MODE == 2) x = x + sc;
        __nv_bfloat16 h = __float2bfloat16(x);
        H[(long long)(ty + i) * C + tx] = h;
        L[(long long)(ty + i) * C + tx] = __float2bfloat16(x - __bfloat162float(h));
    }
}

// ---------------- BN stats / gather(+bias) / fused softmax / reduce ----------
__global__ void __launch_bounds__(256) bn_stats_kernel(
    const float* __restrict__ x, const float* __restrict__ gamma,
    const float* __restrict__ beta, float* __restrict__ scale,
    float* __restrict__ shift, int Cd)
{
    __shared__ float rs[8], rq[8];
    int c = blockIdx.x, t = threadIdx.x;
    float s = 0.f, q = 0.f;
    for (int b = 0; b < BATCH; ++b) {
        const float4* p = reinterpret_cast<const float4*>(x + ((long long)b * Cd + c) * NPTS);
        for (int v = t; v < NPTS / 4; v += 256) {
            float4 f = p[v];
            s += f.x + f.y + f.z + f.w;
            q += f.x * f.x + f.y * f.y + f.z * f.z + f.w * f.w;
        }
    }
#pragma unroll
    for (int o = 16; o; o >>= 1) {
        s += __shfl_xor_sync(0xFFFFFFFFu, s, o);
        q += __shfl_xor_sync(0xFFFFFFFFu, q, o);
    }
    if ((t & 31) == 0) { rs[t >> 5] = s; rq[t >> 5] = q; }
    __syncthreads();
    if (t == 0) {
        float S = 0.f, Q = 0.f;
#pragma unroll
        for (int w = 0; w < 8; ++w) { S += rs[w]; Q += rq[w]; }
        const float inv = 1.f / (float)(BATCH * NPTS);
        float mean = S * inv, var = Q * inv - mean * mean;
        float rstd = rsqrtf(var + 1e-5f), g = gamma[c];
        scale[c] = rstd * g;
        shift[c] = beta[c] - mean * rstd * g;
    }
}

__global__ void __launch_bounds__(256) gather_kernel(
    const float* __restrict__ xyz, float* __restrict__ out_xyz,
    const float* __restrict__ b3)
{
    int v = blockIdx.x * blockDim.x + threadIdx.x;
    if (v < BATCH * 256 * NCENT) {
        int b = v >> 17, rem = v & 131071, c = rem >> 9, m = rem & 511;
        int id = g_idx[b * NCENT + m];
        float f = g_feat[((long long)b * 256 + c) * NPTS + id];
        f += b3[c];
        g_cent[v] = f;
    }
    if (v < BATCH * 3 * NCENT) {
        int b = v / (3 * NCENT), rem = v - b * 3 * NCENT, c = rem >> 9, m = rem & 511;
        int id = g_idx[b * NCENT + m];
        out_xyz[v] = xyz[((long long)b * 3 + c) * NPTS + id];
    }
}

// softmax over N, writes bf16 hi/lo probs directly (fused split)
__global__ void __launch_bounds__(256) softmax_kernel()
{
    __shared__ float red[8];
    long long row = blockIdx.x;
    const float4* p = reinterpret_cast<const float4*>(g_logits + row * NPTS);
    __nv_bfloat162* PH = reinterpret_cast<__nv_bfloat162*>(g_ph + row * NPTS);
    __nv_bfloat162* PL = reinterpret_cast<__nv_bfloat162*>(g_pl + row * NPTS);
    int t = threadIdx.x;
    float4 v[8];
#pragma unroll
    for (int i = 0; i < 8; ++i) v[i] = p[t + (i << 8)];
    float mx = -1e30f;
#pragma unroll
    for (int i = 0; i < 8; ++i)
        mx = fmaxf(mx, fmaxf(fmaxf(v[i].x, v[i].y), fmaxf(v[i].z, v[i].w)));
#pragma unroll
    for (int o = 16; o; o >>= 1) mx = fmaxf(mx, __shfl_xor_sync(0xFFFFFFFFu, mx, o));
    if ((t & 31) == 0) red[t >> 5] = mx;
    __syncthreads();
#pragma unroll
    for (int w = 0; w < 8; ++w) mx = fmaxf(mx, red[w]);
    __syncthreads();
    float s = 0.f;
#pragma unroll
    for (int i = 0; i < 8; ++i) {
        v[i].x = __expf(v[i].x - mx); v[i].y = __expf(v[i].y - mx);
        v[i].z = __expf(v[i].z - mx); v[i].w = __expf(v[i].w - mx);
        s += v[i].x + v[i].y + v[i].z + v[i].w;
    }
#pragma unroll
    for (int o = 16; o; o >>= 1) s += __shfl_xor_sync(0xFFFFFFFFu, s, o);
    if ((t & 31) == 0) red[t >> 5] = s;
    __syncthreads();
    s = 0.f;
#pragma unroll
    for (int w = 0; w < 8; ++w) s += red[w];
    float inv = 1.f / s;
#pragma unroll
    for (int i = 0; i < 8; ++i) {
        float x0 = v[i].x * inv, x1 = v[i].y * inv;
        float x2 = v[i].z * inv, x3 = v[i].w * inv;
        __nv_bfloat16 h0 = __float2bfloat16(x0), h1 = __float2bfloat16(x1);
        __nv_bfloat16 h2 = __float2bfloat16(x2), h3 = __float2bfloat16(x3);
        __nv_bfloat162 a, bb;
        a.x = h0; a.y = h1; bb.x = h2; bb.y = h3;
        int idx = (t + (i << 8)) * 2;
        PH[idx] = a; PH[idx + 1] = bb;
        a.x = __float2bfloat16(x0 - __bfloat162float(h0));
        a.y = __float2bfloat16(x1 - __bfloat162float(h1));
        bb.x = __float2bfloat16(x2 - __bfloat162float(h2));
        bb.y = __float2bfloat16(x3 - __bfloat162float(h3));
        PL[idx] = a; PL[idx + 1] = bb;
    }
}

__global__ void __launch_bounds__(256) reduceK_kernel()
{
    int v = blockIdx.x * blockDim.x + threadIdx.x;
    int total = BATCH * 256 * NCENT / 4;
    if (v >= total) return;
    int b = v >> 15, i = v & 32767;
    const float4* pp = reinterpret_cast<const float4*>(g_attpart);
    float4 s = pp[((long long)b * KSPLIT_PV + 0) * 32768 + i];
#pragma unroll
    for (int ks = 1; ks < KSPLIT_PV; ++ks) {
        float4 x = pp[((long long)b * KSPLIT_PV + ks) * 32768 + i];
        s.x += x.x; s.y += x.y; s.z += x.z; s.w += x.w;
    }
    reinterpret_cast<float4*>(g_att)[v] = s;
}

// ---------------- host launcher ---------------------------------------------
static float* sym(const void* s) { void* p = nullptr; cudaGetSymbolAddress(&p, (const void*)s); return (float*)p; }
static __nv_bfloat16* symb(const void* s) { void* p = nullptr; cudaGetSymbolAddress(&p, (const void*)s); return (__nv_bfloat16*)p; }

extern "C" void kernel_launch(void* const* d_in, const int* in_sizes, int n_in,
                              void* d_out, int out_size)
{
    const float* xyz = (const float*)d_in[0];
    const float* pf  = (const float*)d_in[1];
    const float* w1  = (const float*)d_in[2];
    const float* b1  = (const float*)d_in[3];
    const float* g1  = (const float*)d_in[4];
    const float* be1 = (const float*)d_in[5];
    const float* w2  = (const float*)d_in[6];
    const float* g2  = (const float*)d_in[8];
    const float* be2 = (const float*)d_in[9];
    const float* w3  = (const float*)d_in[10];
    const float* b3  = (const float*)d_in[11];
    const float* wq  = (const float*)d_in[12];
    const float* wk  = (const float*)d_in[13];
    const float* wv  = (const float*)d_in[14];
    const float* wo  = (const float*)d_in[15];
    const int*   far0 = (const int*)d_in[16];
    float* out = (float*)d_out;

    float* p_sup = sym(g_support); float* p_h1 = sym(g_h1); float* p_h2 = sym(g_h2);
    float* p_feat = sym(g_feat); float* p_k = sym(g_kbuf); float* p_v = sym(g_vbuf);
    float* p_q = sym(g_qbuf); float* p_cent = sym(g_cent); float* p_log = sym(g_logits);
    float* p_ap = sym(g_attpart); float* p_att = sym(g_att);
    float* p_s1 = sym(g_bns1); float* p_sh1 = sym(g_bnh1);
    float* p_s2 = sym(g_bns2); float* p_sh2 = sym(g_bnh2);

    __nv_bfloat16 *w2h = symb(g_w2h), *w2l = symb(g_w2l), *w3h = symb(g_w3h), *w3l = symb(g_w3l);
    __nv_bfloat16 *wkh = symb(g_wkh), *wkl = symb(g_wkl), *wvh = symb(g_wvh), *wvl = symb(g_wvl);
    __nv_bfloat16 *h1Th = symb(g_h1Th), *h1Tl = symb(g_h1Tl), *h2Th = symb(g_h2Th), *h2Tl = symb(g_h2Tl);
    __nv_bfloat16 *fTh = symb(g_fTh), *fTl = symb(g_fTl), *kTh = symb(g_kTh), *kTl = symb(g_kTl);
    __nv_bfloat16 *vh = symb(g_vh), *vl = symb(g_vl), *qTh = symb(g_qTh), *qTl = symb(g_qTl);
    __nv_bfloat16 *ph = symb(g_ph), *pl = symb(g_pl);

    fps_init_kernel<<<1, 64>>>();
    support_kernel<<<1024, 256>>>(xyz, pf);
    fps_kernel<<<128, 512>>>(far0);

    // weight splits
    split_kernel<<<32, 256>>>(w2, w2h, w2l, 256 * 128 / 4);
    split_kernel<<<64, 256>>>(w3, w3h, w3l, 256 * 256 / 4);
    split_kernel<<<64, 256>>>(wk, wkh, wkl, 256 * 256 / 4);
    split_kernel<<<64, 256>>>(wv, wvh, wvl, 256 * 256 / 4);

    // h1 = w1 @ support + b1 (fp32); BN1 stats; fused BN+lrelu transpose-split
    sgemm_kernel<<<dim3(64, 1, 8), 256>>>(w1, p_sup, p_h1, NPTS, 64,
        64LL * NPTS, 128LL * NPTS, b1, nullptr, 1.f);
    bn_stats_kernel<<<128, 256>>>(p_h1, g1, be1, p_s1, p_sh1, 128);
    tsplit_kernel<1><<<dim3(256, 4, 8), 256>>>(p_h1, h1Th, h1Tl, p_s1, p_sh1, 128, NPTS);

    // h2 = w2 @ h1' (tc; b2 cancels in BN); BN2 stats; fused tsplit
    tc_gemm_kernel<<<dim3(64, 2, 8), 256>>>(w2h, w2l, h1Th, h1Tl, p_h2,
        NPTS, 128, 0LL, (long long)NPTS * 128, 256LL * NPTS, 1.f, 1);
    bn_stats_kernel<<<256, 256>>>(p_h2, g2, be2, p_s2, p_sh2, 256);
    tsplit_kernel<1><<<dim3(256, 8, 8), 256>>>(p_h2, h2Th, h2Tl, p_s2, p_sh2, 256, NPTS);

    // feat_nb = w3 @ h2' (tc); gather adds b3; tsplit adds b3
    tc_gemm_kernel<<<dim3(64, 2, 8), 256>>>(w3h, w3l, h2Th, h2Tl, p_feat,
        NPTS, 256, 0LL, (long long)NPTS * 256, 256LL * NPTS, 1.f, 1);
    gather_kernel<<<4096, 256>>>(xyz, out, b3);
    tsplit_kernel<2><<<dim3(256, 8, 8), 256>>>(p_feat, fTh, fTl, b3, nullptr, 256, NPTS);

    // k, v (tc)
    tc_gemm_kernel<<<dim3(64, 2, 8), 256>>>(wkh, wkl, fTh, fTl, p_k,
        NPTS, 256, 0LL, (long long)NPTS * 256, 256LL * NPTS, 1.f, 1);
    tc_gemm_kernel<<<dim3(64, 2, 8), 256>>>(wvh, wvl, fTh, fTl, p_v,
        NPTS, 256, 0LL, (long long)NPTS * 256, 256LL * NPTS, 1.f, 1);
    tsplit_kernel<0><<<dim3(256, 8, 8), 256>>>(p_k, kTh, kTl, nullptr, nullptr, 256, NPTS);
    split_kernel<<<4096, 256>>>(p_v, vh, vl, BATCH * 256 * NPTS / 4);

    // q = wq @ centroids (fp32); transpose-split
    sgemm_kernel<<<dim3(4, 2, 8), 256>>>(wq, p_cent, p_q, NCENT, 256,
        256LL * NCENT, 256LL * NCENT, nullptr, nullptr, 1.f);
    tsplit_kernel<0><<<dim3(16, 8, 8), 256>>>(p_q, qTh, qTl, nullptr, nullptr, 256, NCENT);

    // logits = (q^T k) / 16 (tc)
    tc_gemm_kernel<<<dim3(64, 4, 8), 256>>>(qTh, qTl, kTh, kTl, p_log,
        NPTS, 256, (long long)NCENT * 256, (long long)NPTS * 256,
        (long long)NCENT * NPTS, 0.0625f, 1);

    // softmax (writes bf16 hi/lo probs directly)
    softmax_kernel<<<BATCH * NCENT, 256>>>();

    // att = probs @ v^T (tc, split-K 8)
    tc_gemm_kernel<<<dim3(4, 2, 8 * KSPLIT_PV), 256>>>(vh, vl, ph, pl, p_ap,
        NCENT, NPTS, 256LL * NPTS, (long long)NCENT * NPTS, 256LL * NCENT,
        1.f, KSPLIT_PV);
    reduceK_kernel<<<1024, 256>>>();

    // out2 = centroids + wo @ att (fp32)
    sgemm_kernel<<<dim3(4, 2, 8), 256>>>(wo, p_att, out + BATCH * 3 * NCENT, NCENT, 256,
        256LL * NCENT, 256LL * NCENT, nullptr, p_cent, 1.f);
}